// round 4
// baseline (speedup 1.0000x reference)
#include <cuda_runtime.h>
#include <math.h>

// ---------------- problem constants ----------------
#define BN  4
#define CIN 768
#define FC  256
#define N0  1024   // 32*32

// ---------------- scratch (device globals; no allocations allowed) ----------------
__device__ float g_x0 [BN*FC*N0];          //  4 MB fused features (B,256,32,32)
__device__ float g_enh[BN*FC*N0];          //  4 MB enhanced
__device__ float g_off[BN*32*64*64];       //  2 MB offsets (max stage-2 size)
__device__ float g_up [BN*FC*128*128];     // 64 MB upsampled (shared by both stages)
__device__ float g_c1 [BN*FC*64*64];       // 16 MB conv1 output
__device__ float g_c2 [BN*FC*128*128];     // 64 MB conv2 output

__device__ __forceinline__ float gelu_exact(float x) {
    return 0.5f * x * (1.0f + erff(x * 0.70710678118654752440f));
}

// =====================================================================
// Kernel 1: weighted fusion.  out[b,f,n] = sum_l lw[l]*gelu( X_l^T W_l )
// GEMM: M=4096 (b,n), N=256 (f), K=768, x4 layers. 64x64 tile, 4x4 micro.
// =====================================================================
__global__ __launch_bounds__(256)
void fusion_kernel(const float* __restrict__ f1, const float* __restrict__ f2,
                   const float* __restrict__ f3, const float* __restrict__ f4,
                   const float* __restrict__ pw, const float* __restrict__ lwr,
                   float* __restrict__ out) {
    __shared__ float As[16][64];
    __shared__ float Bs[16][64];
    const float* fs[4] = {f1, f2, f3, f4};

    // softmax over 4 layer weights (redundant per thread, trivial)
    float l0 = __ldg(lwr), l1 = __ldg(lwr+1), l2 = __ldg(lwr+2), l3 = __ldg(lwr+3);
    float mx = fmaxf(fmaxf(l0,l1), fmaxf(l2,l3));
    float e0 = expf(l0-mx), e1 = expf(l1-mx), e2 = expf(l2-mx), e3 = expf(l3-mx);
    float inv = 1.0f/(e0+e1+e2+e3);
    float lw[4] = {e0*inv, e1*inv, e2*inv, e3*inv};

    int tid = threadIdx.x;
    int tx = tid & 15, ty = tid >> 4;
    int m0 = blockIdx.x * 64;          // (b,n) tile
    int fo0 = blockIdx.y * 64;         // f tile
    int b  = m0 >> 10;
    int nb = m0 & 1023;
    int lm = tid & 63;                 // load column
    int lk = tid >> 6;                 // load row base (0..3)

    float outacc[4][4];
    #pragma unroll
    for (int i=0;i<4;i++)
        #pragma unroll
        for (int j=0;j<4;j++) outacc[i][j]=0.f;

    #pragma unroll
    for (int l = 0; l < 4; l++) {
        const float* A  = fs[l] + b * CIN * N0 + nb;   // (C,N) slab for batch b
        const float* Wl = pw + l * CIN * FC + fo0;     // (C,F)
        float acc[4][4];
        #pragma unroll
        for (int i=0;i<4;i++)
            #pragma unroll
            for (int j=0;j<4;j++) acc[i][j]=0.f;

        for (int k0 = 0; k0 < CIN; k0 += 16) {
            #pragma unroll
            for (int i = 0; i < 4; i++) {
                int kk = lk + i*4;
                As[kk][lm] = A [(k0+kk)*N0 + lm];
                Bs[kk][lm] = Wl[(k0+kk)*FC + lm];
            }
            __syncthreads();
            #pragma unroll
            for (int kk = 0; kk < 16; kk++) {
                float4 av = *(const float4*)&As[kk][tx*4];
                float4 bv = *(const float4*)&Bs[kk][ty*4];
                float a[4] = {av.x,av.y,av.z,av.w};
                float bb[4] = {bv.x,bv.y,bv.z,bv.w};
                #pragma unroll
                for (int i=0;i<4;i++)
                    #pragma unroll
                    for (int j=0;j<4;j++)
                        acc[i][j] = fmaf(a[i], bb[j], acc[i][j]);
            }
            __syncthreads();
        }
        float wl = lw[l];
        #pragma unroll
        for (int i=0;i<4;i++)
            #pragma unroll
            for (int j=0;j<4;j++)
                outacc[i][j] = fmaf(wl, gelu_exact(acc[i][j]), outacc[i][j]);
    }
    // write NCHW: out[(b*256+f)*1024 + n]
    #pragma unroll
    for (int j = 0; j < 4; j++) {
        int f = fo0 + ty*4 + j;
        float4 v = make_float4(outacc[0][j], outacc[1][j], outacc[2][j], outacc[3][j]);
        *(float4*)&out[(b*FC + f)*N0 + nb + tx*4] = v;
    }
}

// =====================================================================
// Kernel 2: depthwise 3x3 + BN + residual ReLU (32x32)
// =====================================================================
__global__ __launch_bounds__(256)
void enhance_kernel(const float* __restrict__ x, const float* __restrict__ dw,
                    const float* __restrict__ bnp, float* __restrict__ out) {
    int idx = blockIdx.x * 256 + threadIdx.x;      // B*256*1024
    int s = idx & 1023;
    int w = s & 31, h = s >> 5;
    int f = (idx >> 10) & 255;
    float xc = x[idx];
    const float* base = x + (idx - s);
    float y = 0.f;
    #pragma unroll
    for (int kh = 0; kh < 3; kh++) {
        int iy = h + kh - 1;
        if ((unsigned)iy < 32u) {
            #pragma unroll
            for (int kw = 0; kw < 3; kw++) {
                int ix = w + kw - 1;
                if ((unsigned)ix < 32u)
                    y = fmaf(__ldg(&dw[f*9 + kh*3 + kw]), base[iy*32 + ix], y);
            }
        }
    }
    float g  = __ldg(&bnp[f]),       be = __ldg(&bnp[256+f]);
    float mu = __ldg(&bnp[512+f]),   va = __ldg(&bnp[768+f]);
    float sc = g * rsqrtf(va + 1e-5f);
    out[idx] = fmaxf(fmaf(y - mu, sc, be) + xc, 0.f);
}

// =====================================================================
// Kernel 3: 1x1 offset conv (256 -> 32) + bias
// =====================================================================
__global__ __launch_bounds__(256)
void offset_kernel(const float* __restrict__ in, const float* __restrict__ ow,
                   const float* __restrict__ ob, float* __restrict__ off,
                   int H, int W) {
    int HW = H*W;
    int idx = blockIdx.x*256 + threadIdx.x;   // B*32*HW
    int s  = idx % HW;
    int ch = (idx / HW) & 31;
    int b  = idx / (32*HW);
    const float* ip = in + b*FC*HW + s;
    const float* wp = ow + ch*FC;
    float acc = __ldg(&ob[ch]);
    #pragma unroll 8
    for (int c = 0; c < FC; c++)
        acc = fmaf(__ldg(&wp[c]), ip[c*HW], acc);
    off[idx] = acc;
}

// =====================================================================
// Kernel 4: DySample bilinear gather (2x upsample).
// px = clamp(w + offx, 0, W-1); py = clamp(h + offy, 0, H-1)
// offx = off[b, g*4+dh*2+dw, h, w]*0.25 + (0.5*dw - 0.25)   (offy: +16 ch, dh)
// =====================================================================
__global__ __launch_bounds__(256)
void upsample_kernel(const float* __restrict__ x, const float* __restrict__ off,
                     float* __restrict__ out, int H, int W) {
    int W2 = 2*W, H2 = 2*H;
    int HW = H*W;
    int idx = blockIdx.x*256 + threadIdx.x;   // B*256*H2*W2
    int wo = idx % W2;
    int t  = idx / W2;
    int ho = t % H2; t /= H2;
    int c  = t & 255;
    int b  = t >> 8;
    int g  = c >> 6;
    int h = ho >> 1, dh = ho & 1, w = wo >> 1, dw = wo & 1;
    int ch0 = g*4 + dh*2 + dw;
    int obase = ((b*32 + ch0)*H + h)*W + w;
    float offx = off[obase]         * 0.25f + (0.5f*(float)dw - 0.25f);
    float offy = off[obase + 16*HW] * 0.25f + (0.5f*(float)dh - 0.25f);
    float px = fminf(fmaxf((float)w + offx, 0.f), (float)(W-1));
    float py = fminf(fmaxf((float)h + offy, 0.f), (float)(H-1));
    int x0 = (int)px;            // floor (px >= 0)
    int y0 = (int)py;
    float wx = px - (float)x0, wy = py - (float)y0;
    int x1 = min(x0+1, W-1);
    int y1 = min(y0+1, H-1);
    const float* ib = x + (b*FC + c)*HW;
    float v00 = ib[y0*W + x0], v01 = ib[y0*W + x1];
    float v10 = ib[y1*W + x0], v11 = ib[y1*W + x1];
    float v0 = v00 + (v01 - v00)*wx;
    float v1 = v10 + (v11 - v10)*wx;
    out[idx] = v0 + (v1 - v0)*wy;
}

// =====================================================================
// Kernel 5: 3x3 conv 256->256 as implicit GEMM + BN + ReLU.
// M = B*H*W, N = 256, K = 2304. 128x128 tile, KT=16, 8x8 micro (4+4 split).
// =====================================================================
__global__ __launch_bounds__(256, 2)
void conv3x3_gemm(const float* __restrict__ in, const float* __restrict__ wgt,
                  const float* __restrict__ bnp, float* __restrict__ out,
                  int H, int W) {
    const int HW = H*W;
    __shared__ float As[16][128];
    __shared__ float Bs[16][132];   // padded: kills 16-way store conflict

    int tid = threadIdx.x;
    int m0 = blockIdx.x * 128;
    int n0 = blockIdx.y * 128;

    // --- A (im2col) load mapping: mm fixed per thread, kk = a_k0 + 2*i ---
    int a_mm = tid & 127;
    int a_k0 = tid >> 7;                 // 0 or 1
    int m = m0 + a_mm;
    int b = m / HW;
    int s = m - b*HW;
    int y  = s / W;
    int xw = s - y*W;
    const float* inb = in + b*FC*HW;

    // --- B load mapping: kk = tid&15 (contiguous global reads), nn strided ---
    int b_kk  = tid & 15;
    int b_nn0 = tid >> 4;

    int tx = tid & 15, ty = tid >> 4;

    float acc[8][8];
    #pragma unroll
    for (int i=0;i<8;i++)
        #pragma unroll
        for (int j=0;j<8;j++) acc[i][j]=0.f;

    for (int k0 = 0; k0 < 2304; k0 += 16) {
        #pragma unroll
        for (int i = 0; i < 8; i++) {
            int kk = a_k0 + 2*i;
            int k  = k0 + kk;
            int c  = k / 9;
            int r  = k - c*9;
            int kh = r / 3;
            int kw = r - kh*3;
            int iy = y + kh - 1;
            int ix = xw + kw - 1;
            float v = 0.f;
            if ((unsigned)iy < (unsigned)H && (unsigned)ix < (unsigned)W)
                v = inb[c*HW + iy*W + ix];
            As[kk][a_mm] = v;
        }
        #pragma unroll
        for (int i = 0; i < 8; i++) {
            int nn = b_nn0 + i*16;
            Bs[b_kk][nn] = wgt[(n0+nn)*2304 + k0 + b_kk];
        }
        __syncthreads();
        #pragma unroll
        for (int kk = 0; kk < 16; kk++) {
            float4 a0 = *(const float4*)&As[kk][tx*4];
            float4 a1 = *(const float4*)&As[kk][64 + tx*4];
            float4 b0 = *(const float4*)&Bs[kk][ty*4];
            float4 b1 = *(const float4*)&Bs[kk][64 + ty*4];
            float a[8] = {a0.x,a0.y,a0.z,a0.w, a1.x,a1.y,a1.z,a1.w};
            float bb[8] = {b0.x,b0.y,b0.z,b0.w, b1.x,b1.y,b1.z,b1.w};
            #pragma unroll
            for (int i=0;i<8;i++)
                #pragma unroll
                for (int j=0;j<8;j++)
                    acc[i][j] = fmaf(a[i], bb[j], acc[i][j]);
        }
        __syncthreads();
    }

    // epilogue: BN + ReLU, NCHW writes (float4 along spatial)
    float scale[8], shift[8];
    #pragma unroll
    for (int jj = 0; jj < 8; jj++) {
        int n = n0 + ((jj < 4) ? (ty*4 + jj) : (64 + ty*4 + jj - 4));
        float g  = __ldg(&bnp[n]),     be = __ldg(&bnp[256+n]);
        float mu = __ldg(&bnp[512+n]), va = __ldg(&bnp[768+n]);
        scale[jj] = g * rsqrtf(va + 1e-5f);
        shift[jj] = be - mu*scale[jj];
    }
    #pragma unroll
    for (int rg = 0; rg < 2; rg++) {
        int mrow = m0 + rg*64 + tx*4;
        int bb_ = mrow / HW;
        int ss  = mrow - bb_*HW;
        #pragma unroll
        for (int jj = 0; jj < 8; jj++) {
            int n = n0 + ((jj < 4) ? (ty*4 + jj) : (64 + ty*4 + jj - 4));
            float4 v;
            v.x = fmaxf(fmaf(acc[rg*4+0][jj], scale[jj], shift[jj]), 0.f);
            v.y = fmaxf(fmaf(acc[rg*4+1][jj], scale[jj], shift[jj]), 0.f);
            v.z = fmaxf(fmaf(acc[rg*4+2][jj], scale[jj], shift[jj]), 0.f);
            v.w = fmaxf(fmaf(acc[rg*4+3][jj], scale[jj], shift[jj]), 0.f);
            *(float4*)&out[(bb_*FC + n)*HW + ss] = v;
        }
    }
}

// =====================================================================
// Kernel 6: head conv 3x3, 256 -> 1, + bias
// =====================================================================
__global__ __launch_bounds__(256)
void outconv_kernel(const float* __restrict__ in, const float* __restrict__ wv,
                    const float* __restrict__ bias, float* __restrict__ out,
                    int H, int W) {
    __shared__ float ws[FC*9];
    int tid = threadIdx.x;
    for (int i = tid; i < FC*9; i += 256) ws[i] = wv[i];
    __syncthreads();
    int HW = H*W;
    int idx = blockIdx.x*256 + tid;
    int s = idx % HW;
    int b = idx / HW;
    int y = s / W, xw = s % W;
    const float* base = in + b*FC*HW;
    float acc = __ldg(bias);
    for (int c = 0; c < FC; c++) {
        const float* ip = base + c*HW;
        const float* wc = ws + c*9;
        #pragma unroll
        for (int kh = 0; kh < 3; kh++) {
            int iy = y + kh - 1;
            if ((unsigned)iy < (unsigned)H) {
                #pragma unroll
                for (int kw = 0; kw < 3; kw++) {
                    int ix = xw + kw - 1;
                    if ((unsigned)ix < (unsigned)W)
                        acc = fmaf(wc[kh*3+kw], ip[iy*W + ix], acc);
                }
            }
        }
    }
    out[idx] = acc;
}

// =====================================================================
// launcher
// =====================================================================
extern "C" void kernel_launch(void* const* d_in, const int* in_sizes, int n_in,
                              void* d_out, int out_size) {
    const float* f1  = (const float*)d_in[0];
    const float* f2  = (const float*)d_in[1];
    const float* f3  = (const float*)d_in[2];
    const float* f4  = (const float*)d_in[3];
    const float* pw  = (const float*)d_in[4];
    const float* lw  = (const float*)d_in[5];
    const float* dww = (const float*)d_in[6];
    const float* bne = (const float*)d_in[7];
    const float* ow1 = (const float*)d_in[8];
    const float* ob1 = (const float*)d_in[9];
    const float* cw1 = (const float*)d_in[10];
    const float* bn1 = (const float*)d_in[11];
    const float* ow2 = (const float*)d_in[12];
    const float* ob2 = (const float*)d_in[13];
    const float* cw2 = (const float*)d_in[14];
    const float* bn2 = (const float*)d_in[15];
    const float* owv = (const float*)d_in[16];
    const float* obv = (const float*)d_in[17];
    float* outp = (float*)d_out;

    float *px0, *penh, *poff, *pup, *pc1, *pc2;
    cudaGetSymbolAddress((void**)&px0,  g_x0);
    cudaGetSymbolAddress((void**)&penh, g_enh);
    cudaGetSymbolAddress((void**)&poff, g_off);
    cudaGetSymbolAddress((void**)&pup,  g_up);
    cudaGetSymbolAddress((void**)&pc1,  g_c1);
    cudaGetSymbolAddress((void**)&pc2,  g_c2);

    // 1) weighted fusion GEMM + GELU  -> (B,256,32,32)
    fusion_kernel<<<dim3(64, 4), 256>>>(f1, f2, f3, f4, pw, lw, px0);
    // 2) depthwise enhancer
    enhance_kernel<<<4096, 256>>>(px0, dww, bne, penh);
    // 3) stage 1: offsets, upsample to 64x64, conv+BN+ReLU
    offset_kernel  <<<512,   256>>>(penh, ow1, ob1, poff, 32, 32);
    upsample_kernel<<<16384, 256>>>(penh, poff, pup, 32, 32);
    conv3x3_gemm   <<<dim3(128, 2), 256>>>(pup, cw1, bn1, pc1, 64, 64);
    // 4) stage 2: offsets, upsample to 128x128, conv+BN+ReLU
    offset_kernel  <<<2048,  256>>>(pc1, ow2, ob2, poff, 64, 64);
    upsample_kernel<<<65536, 256>>>(pc1, poff, pup, 64, 64);
    conv3x3_gemm   <<<dim3(512, 2), 256>>>(pup, cw2, bn2, pc2, 128, 128);
    // 5) depth head
    outconv_kernel <<<256, 256>>>(pc2, owv, obv, outp, 128, 128);
}

// round 6
// speedup vs baseline: 1.1410x; 1.1410x over previous
#include <cuda_runtime.h>
#include <math.h>

// ---------------- problem constants ----------------
#define BN  4
#define CIN 768
#define FC  256
#define N0  1024   // 32*32

// ---------------- scratch (device globals; no allocations allowed) ----------------
__device__ float g_x0 [BN*FC*N0];          //  4 MB fused features (B,256,32,32)
__device__ float g_enh[BN*FC*N0];          //  4 MB enhanced
__device__ float g_off[BN*32*64*64];       //  2 MB offsets (max stage-2 size)
__device__ float g_up [BN*FC*128*128];     // 64 MB upsampled (shared by both stages)
__device__ float g_c1 [BN*FC*64*64];       // 16 MB conv1 output
__device__ float g_c2 [BN*FC*128*128];     // 64 MB conv2 output

__device__ __forceinline__ float gelu_exact(float x) {
    return 0.5f * x * (1.0f + erff(x * 0.70710678118654752440f));
}

// ---------------- packed fp32x2 helpers (FFMA2 path, sm_103a) ----------------
typedef unsigned long long ull;

__device__ __forceinline__ ull pack_dup(float a) {
    ull r; asm("mov.b64 %0, {%1, %1};" : "=l"(r) : "f"(a)); return r;
}
__device__ __forceinline__ void unpack2(float& lo, float& hi, ull v) {
    asm("mov.b64 {%0, %1}, %2;" : "=f"(lo), "=f"(hi) : "l"(v));
}
#define FFMA2(d, a, b) asm("fma.rn.f32x2 %0, %1, %2, %0;" : "+l"(d) : "l"(a), "l"(b))

// =====================================================================
// Kernel 1: weighted fusion.  out[b,f,n] = sum_l lw[l]*gelu( X_l^T W_l )
// GEMM: M=4096 (b,n), N=256 (f), K=768, x4 layers. 64x64 tile, 4x4 micro.
// =====================================================================
__global__ __launch_bounds__(256)
void fusion_kernel(const float* __restrict__ f1, const float* __restrict__ f2,
                   const float* __restrict__ f3, const float* __restrict__ f4,
                   const float* __restrict__ pw, const float* __restrict__ lwr,
                   float* __restrict__ out) {
    __shared__ float As[16][64];
    __shared__ float Bs[16][64];
    const float* fs[4] = {f1, f2, f3, f4};

    // softmax over 4 layer weights (redundant per thread, trivial)
    float l0 = __ldg(lwr), l1 = __ldg(lwr+1), l2 = __ldg(lwr+2), l3 = __ldg(lwr+3);
    float mx = fmaxf(fmaxf(l0,l1), fmaxf(l2,l3));
    float e0 = expf(l0-mx), e1 = expf(l1-mx), e2 = expf(l2-mx), e3 = expf(l3-mx);
    float inv = 1.0f/(e0+e1+e2+e3);
    float lw[4] = {e0*inv, e1*inv, e2*inv, e3*inv};

    int tid = threadIdx.x;
    int tx = tid & 15, ty = tid >> 4;
    int m0 = blockIdx.x * 64;          // (b,n) tile
    int fo0 = blockIdx.y * 64;         // f tile
    int b  = m0 >> 10;
    int nb = m0 & 1023;
    int lm = tid & 63;                 // load column
    int lk = tid >> 6;                 // load row base (0..3)

    float outacc[4][4];
    #pragma unroll
    for (int i=0;i<4;i++)
        #pragma unroll
        for (int j=0;j<4;j++) outacc[i][j]=0.f;

    #pragma unroll
    for (int l = 0; l < 4; l++) {
        const float* A  = fs[l] + b * CIN * N0 + nb;   // (C,N) slab for batch b
        const float* Wl = pw + l * CIN * FC + fo0;     // (C,F)
        ull acc2[4][2];
        #pragma unroll
        for (int i=0;i<4;i++) { acc2[i][0]=0ULL; acc2[i][1]=0ULL; }

        for (int k0 = 0; k0 < CIN; k0 += 16) {
            #pragma unroll
            for (int i = 0; i < 4; i++) {
                int kk = lk + i*4;
                As[kk][lm] = A [(k0+kk)*N0 + lm];
                Bs[kk][lm] = Wl[(k0+kk)*FC + lm];
            }
            __syncthreads();
            #pragma unroll
            for (int kk = 0; kk < 16; kk++) {
                float4 av = *(const float4*)&As[kk][tx*4];
                ulonglong2 bq = *(const ulonglong2*)&Bs[kk][ty*4];
                ull ad[4] = {pack_dup(av.x), pack_dup(av.y),
                             pack_dup(av.z), pack_dup(av.w)};
                #pragma unroll
                for (int i=0;i<4;i++) {
                    FFMA2(acc2[i][0], ad[i], bq.x);
                    FFMA2(acc2[i][1], ad[i], bq.y);
                }
            }
            __syncthreads();
        }
        float wl = lw[l];
        #pragma unroll
        for (int i=0;i<4;i++)
            #pragma unroll
            for (int jp=0;jp<2;jp++) {
                float vlo, vhi;
                unpack2(vlo, vhi, acc2[i][jp]);
                outacc[i][2*jp+0] = fmaf(wl, gelu_exact(vlo), outacc[i][2*jp+0]);
                outacc[i][2*jp+1] = fmaf(wl, gelu_exact(vhi), outacc[i][2*jp+1]);
            }
    }
    // write NCHW: out[(b*256+f)*1024 + n]
    #pragma unroll
    for (int j = 0; j < 4; j++) {
        int f = fo0 + ty*4 + j;
        float4 v = make_float4(outacc[0][j], outacc[1][j], outacc[2][j], outacc[3][j]);
        *(float4*)&out[(b*FC + f)*N0 + nb + tx*4] = v;
    }
}

// =====================================================================
// Kernel 2: depthwise 3x3 + BN + residual ReLU (32x32)
// =====================================================================
__global__ __launch_bounds__(256)
void enhance_kernel(const float* __restrict__ x, const float* __restrict__ dw,
                    const float* __restrict__ bnp, float* __restrict__ out) {
    int idx = blockIdx.x * 256 + threadIdx.x;      // B*256*1024
    int s = idx & 1023;
    int w = s & 31, h = s >> 5;
    int f = (idx >> 10) & 255;
    float xc = x[idx];
    const float* base = x + (idx - s);
    float y = 0.f;
    #pragma unroll
    for (int kh = 0; kh < 3; kh++) {
        int iy = h + kh - 1;
        if ((unsigned)iy < 32u) {
            #pragma unroll
            for (int kw = 0; kw < 3; kw++) {
                int ix = w + kw - 1;
                if ((unsigned)ix < 32u)
                    y = fmaf(__ldg(&dw[f*9 + kh*3 + kw]), base[iy*32 + ix], y);
            }
        }
    }
    float g  = __ldg(&bnp[f]),       be = __ldg(&bnp[256+f]);
    float mu = __ldg(&bnp[512+f]),   va = __ldg(&bnp[768+f]);
    float sc = g * rsqrtf(va + 1e-5f);
    out[idx] = fmaxf(fmaf(y - mu, sc, be) + xc, 0.f);
}

// =====================================================================
// Kernel 3: 1x1 offset conv (256 -> 32) + bias
// =====================================================================
__global__ __launch_bounds__(256)
void offset_kernel(const float* __restrict__ in, const float* __restrict__ ow,
                   const float* __restrict__ ob, float* __restrict__ off,
                   int H, int W) {
    int HW = H*W;
    int idx = blockIdx.x*256 + threadIdx.x;   // B*32*HW
    int s  = idx % HW;
    int ch = (idx / HW) & 31;
    int b  = idx / (32*HW);
    const float* ip = in + b*FC*HW + s;
    const float* wp = ow + ch*FC;
    float acc = __ldg(&ob[ch]);
    #pragma unroll 8
    for (int c = 0; c < FC; c++)
        acc = fmaf(__ldg(&wp[c]), ip[c*HW], acc);
    off[idx] = acc;
}

// =====================================================================
// Kernel 4: DySample bilinear gather (2x upsample).
// =====================================================================
__global__ __launch_bounds__(256)
void upsample_kernel(const float* __restrict__ x, const float* __restrict__ off,
                     float* __restrict__ out, int H, int W) {
    int W2 = 2*W, H2 = 2*H;
    int HW = H*W;
    int idx = blockIdx.x*256 + threadIdx.x;   // B*256*H2*W2
    int wo = idx % W2;
    int t  = idx / W2;
    int ho = t % H2; t /= H2;
    int c  = t & 255;
    int b  = t >> 8;
    int g  = c >> 6;
    int h = ho >> 1, dh = ho & 1, w = wo >> 1, dw = wo & 1;
    int ch0 = g*4 + dh*2 + dw;
    int obase = ((b*32 + ch0)*H + h)*W + w;
    float offx = off[obase]         * 0.25f + (0.5f*(float)dw - 0.25f);
    float offy = off[obase + 16*HW] * 0.25f + (0.5f*(float)dh - 0.25f);
    float px = fminf(fmaxf((float)w + offx, 0.f), (float)(W-1));
    float py = fminf(fmaxf((float)h + offy, 0.f), (float)(H-1));
    int x0 = (int)px;            // floor (px >= 0)
    int y0 = (int)py;
    float wx = px - (float)x0, wy = py - (float)y0;
    int x1 = min(x0+1, W-1);
    int y1 = min(y0+1, H-1);
    const float* ib = x + (b*FC + c)*HW;
    float v00 = ib[y0*W + x0], v01 = ib[y0*W + x1];
    float v10 = ib[y1*W + x0], v11 = ib[y1*W + x1];
    float v0 = v00 + (v01 - v00)*wx;
    float v1 = v10 + (v11 - v10)*wx;
    out[idx] = v0 + (v1 - v0)*wy;
}

// =====================================================================
// Kernel 5: 3x3 conv 256->256 as implicit GEMM + BN + ReLU.
// M = B*H*W, N = 256, K = 2304. 128x128 tile, KT=16, 8x8 micro (4+4 split).
// Inner product via packed fp32x2 FFMA2: 32 FFMA2/kk instead of 64 FFMA.
// =====================================================================
__global__ __launch_bounds__(256, 2)
void conv3x3_gemm(const float* __restrict__ in, const float* __restrict__ wgt,
                  const float* __restrict__ bnp, float* __restrict__ out,
                  int H, int W) {
    const int HW = H*W;
    __shared__ float As[16][128];
    __shared__ float Bs[16][132];   // padded: kills 16-way store conflict (132*4 % 16 == 0)

    int tid = threadIdx.x;
    int m0 = blockIdx.x * 128;
    int n0 = blockIdx.y * 128;

    // --- A (im2col) load mapping: mm fixed per thread, kk = a_k0 + 2*i ---
    int a_mm = tid & 127;
    int a_k0 = tid >> 7;                 // 0 or 1
    int m = m0 + a_mm;
    int b = m / HW;
    int s = m - b*HW;
    int y  = s / W;
    int xw = s - y*W;
    const float* inb = in + b*FC*HW;

    // --- B load mapping: kk = tid&15 (contiguous global reads), nn strided ---
    int b_kk  = tid & 15;
    int b_nn0 = tid >> 4;

    int tx = tid & 15, ty = tid >> 4;

    // accumulators: 8 rows x 4 column-pairs (each ull = two fp32 cols)
    ull acc2[8][4];
    #pragma unroll
    for (int i=0;i<8;i++)
        #pragma unroll
        for (int jp=0;jp<4;jp++) acc2[i][jp]=0ULL;

    for (int k0 = 0; k0 < 2304; k0 += 16) {
        #pragma unroll
        for (int i = 0; i < 8; i++) {
            int kk = a_k0 + 2*i;
            int k  = k0 + kk;
            int c  = k / 9;
            int r  = k - c*9;
            int kh = r / 3;
            int kw = r - kh*3;
            int iy = y + kh - 1;
            int ix = xw + kw - 1;
            float v = 0.f;
            if ((unsigned)iy < (unsigned)H && (unsigned)ix < (unsigned)W)
                v = inb[c*HW + iy*W + ix];
            As[kk][a_mm] = v;
        }
        #pragma unroll
        for (int i = 0; i < 8; i++) {
            int nn = b_nn0 + i*16;
            Bs[b_kk][nn] = wgt[(n0+nn)*2304 + k0 + b_kk];
        }
        __syncthreads();
        #pragma unroll
        for (int kk = 0; kk < 16; kk++) {
            float4 a0 = *(const float4*)&As[kk][tx*4];
            float4 a1 = *(const float4*)&As[kk][64 + tx*4];
            // B pairs come free as 64-bit views of the 16B shared loads
            ulonglong2 bq0 = *(const ulonglong2*)&Bs[kk][ty*4];
            ulonglong2 bq1 = *(const ulonglong2*)&Bs[kk][64 + ty*4];
            ull bp0 = bq0.x, bp1 = bq0.y, bp2 = bq1.x, bp3 = bq1.y;
            ull ad[8] = {pack_dup(a0.x), pack_dup(a0.y), pack_dup(a0.z), pack_dup(a0.w),
                         pack_dup(a1.x), pack_dup(a1.y), pack_dup(a1.z), pack_dup(a1.w)};
            #pragma unroll
            for (int i=0;i<8;i++) {
                FFMA2(acc2[i][0], ad[i], bp0);
                FFMA2(acc2[i][1], ad[i], bp1);
                FFMA2(acc2[i][2], ad[i], bp2);
                FFMA2(acc2[i][3], ad[i], bp3);
            }
        }
        __syncthreads();
    }

    // unpack accumulators: pair jp -> columns j=2*jp (lo), 2*jp+1 (hi)
    float acc[8][8];
    #pragma unroll
    for (int i=0;i<8;i++)
        #pragma unroll
        for (int jp=0;jp<4;jp++)
            unpack2(acc[i][2*jp], acc[i][2*jp+1], acc2[i][jp]);

    // epilogue: BN + ReLU, NCHW writes (float4 along spatial)
    float scale[8], shift[8];
    #pragma unroll
    for (int jj = 0; jj < 8; jj++) {
        int n = n0 + ((jj < 4) ? (ty*4 + jj) : (64 + ty*4 + jj - 4));
        float g  = __ldg(&bnp[n]),     be = __ldg(&bnp[256+n]);
        float mu = __ldg(&bnp[512+n]), va = __ldg(&bnp[768+n]);
        scale[jj] = g * rsqrtf(va + 1e-5f);
        shift[jj] = be - mu*scale[jj];
    }
    #pragma unroll
    for (int rg = 0; rg < 2; rg++) {
        int mrow = m0 + rg*64 + tx*4;
        int bb_ = mrow / HW;
        int ss  = mrow - bb_*HW;
        #pragma unroll
        for (int jj = 0; jj < 8; jj++) {
            int n = n0 + ((jj < 4) ? (ty*4 + jj) : (64 + ty*4 + jj - 4));
            float4 v;
            v.x = fmaxf(fmaf(acc[rg*4+0][jj], scale[jj], shift[jj]), 0.f);
            v.y = fmaxf(fmaf(acc[rg*4+1][jj], scale[jj], shift[jj]), 0.f);
            v.z = fmaxf(fmaf(acc[rg*4+2][jj], scale[jj], shift[jj]), 0.f);
            v.w = fmaxf(fmaf(acc[rg*4+3][jj], scale[jj], shift[jj]), 0.f);
            *(float4*)&out[(bb_*FC + n)*HW + ss] = v;
        }
    }
}

// =====================================================================
// Kernel 6: head conv 3x3, 256 -> 1, + bias
// =====================================================================
__global__ __launch_bounds__(256)
void outconv_kernel(const float* __restrict__ in, const float* __restrict__ wv,
                    const float* __restrict__ bias, float* __restrict__ out,
                    int H, int W) {
    __shared__ float ws[FC*9];
    int tid = threadIdx.x;
    for (int i = tid; i < FC*9; i += 256) ws[i] = wv[i];
    __syncthreads();
    int HW = H*W;
    int idx = blockIdx.x*256 + tid;
    int s = idx % HW;
    int b = idx / HW;
    int y = s / W, xw = s % W;
    const float* base = in + b*FC*HW;
    float acc = __ldg(bias);
    for (int c = 0; c < FC; c++) {
        const float* ip = base + c*HW;
        const float* wc = ws + c*9;
        #pragma unroll
        for (int kh = 0; kh < 3; kh++) {
            int iy = y + kh - 1;
            if ((unsigned)iy < (unsigned)H) {
                #pragma unroll
                for (int kw = 0; kw < 3; kw++) {
                    int ix = xw + kw - 1;
                    if ((unsigned)ix < (unsigned)W)
                        acc = fmaf(wc[kh*3+kw], ip[iy*W + ix], acc);
                }
            }
        }
    }
    out[idx] = acc;
}

// =====================================================================
// launcher
// =====================================================================
extern "C" void kernel_launch(void* const* d_in, const int* in_sizes, int n_in,
                              void* d_out, int out_size) {
    const float* f1  = (const float*)d_in[0];
    const float* f2  = (const float*)d_in[1];
    const float* f3  = (const float*)d_in[2];
    const float* f4  = (const float*)d_in[3];
    const float* pw  = (const float*)d_in[4];
    const float* lw  = (const float*)d_in[5];
    const float* dww = (const float*)d_in[6];
    const float* bne = (const float*)d_in[7];
    const float* ow1 = (const float*)d_in[8];
    const float* ob1 = (const float*)d_in[9];
    const float* cw1 = (const float*)d_in[10];
    const float* bn1 = (const float*)d_in[11];
    const float* ow2 = (const float*)d_in[12];
    const float* ob2 = (const float*)d_in[13];
    const float* cw2 = (const float*)d_in[14];
    const float* bn2 = (const float*)d_in[15];
    const float* owv = (const float*)d_in[16];
    const float* obv = (const float*)d_in[17];
    float* outp = (float*)d_out;

    float *px0, *penh, *poff, *pup, *pc1, *pc2;
    cudaGetSymbolAddress((void**)&px0,  g_x0);
    cudaGetSymbolAddress((void**)&penh, g_enh);
    cudaGetSymbolAddress((void**)&poff, g_off);
    cudaGetSymbolAddress((void**)&pup,  g_up);
    cudaGetSymbolAddress((void**)&pc1,  g_c1);
    cudaGetSymbolAddress((void**)&pc2,  g_c2);

    // 1) weighted fusion GEMM + GELU  -> (B,256,32,32)
    fusion_kernel<<<dim3(64, 4), 256>>>(f1, f2, f3, f4, pw, lw, px0);
    // 2) depthwise enhancer
    enhance_kernel<<<4096, 256>>>(px0, dww, bne, penh);
    // 3) stage 1: offsets, upsample to 64x64, conv+BN+ReLU
    offset_kernel  <<<512,   256>>>(penh, ow1, ob1, poff, 32, 32);
    upsample_kernel<<<16384, 256>>>(penh, poff, pup, 32, 32);
    conv3x3_gemm   <<<dim3(128, 2), 256>>>(pup, cw1, bn1, pc1, 64, 64);
    // 4) stage 2: offsets, upsample to 128x128, conv+BN+ReLU
    offset_kernel  <<<2048,  256>>>(pc1, ow2, ob2, poff, 64, 64);
    upsample_kernel<<<65536, 256>>>(pc1, poff, pup, 64, 64);
    conv3x3_gemm   <<<dim3(512, 2), 256>>>(pup, cw2, bn2, pc2, 128, 128);
    // 5) depth head
    outconv_kernel <<<256, 256>>>(pc2, owv, obv, outp, 128, 128);
}

// round 12
// speedup vs baseline: 1.7361x; 1.5216x over previous
#include <cuda_runtime.h>
#include <cuda_bf16.h>
#include <math.h>
#include <stdint.h>

// ---------------- problem constants ----------------
#define BN  4
#define CIN 768
#define FC  256
#define N0  1024   // 32*32

// ---------------- scratch (device globals; no allocations allowed) ----------------
// HWC layouts: [(b*H + y)*W + x][c]
__device__ float g_x0t [BN*N0*FC];                 //  4 MB fusion out (HWC, 32x32)
__device__ float g_enht[BN*N0*FC];                 //  4 MB enhanced   (HWC, 32x32)
__device__ float g_off [BN*32*64*64];              //  2 MB offsets (NCHW, max stage-2)
__device__ __nv_bfloat16 g_uph[BN*128*128*FC];     // 33.5 MB upsampled hi (HWC bf16)
__device__ __nv_bfloat16 g_upl[BN*128*128*FC];     // 33.5 MB upsampled lo
__device__ float g_c1t [BN*64*64*FC];              // 16 MB conv1 out (HWC)
__device__ float g_c2t [BN*128*128*FC];            // 64 MB conv2 out (HWC)
// pre-split conv weights: [(kh*3+kw)*256 + n][c] bf16
__device__ __nv_bfloat16 g_w1h[9*FC*FC], g_w1l[9*FC*FC];
__device__ __nv_bfloat16 g_w2h[9*FC*FC], g_w2l[9*FC*FC];

__device__ __forceinline__ float gelu_exact(float x) {
    return 0.5f * x * (1.0f + erff(x * 0.70710678118654752440f));
}

// ---------------- packed fp32x2 helpers (fusion kernel) ----------------
typedef unsigned long long ull;
__device__ __forceinline__ ull pack_dup(float a) {
    ull r; asm("mov.b64 %0, {%1, %1};" : "=l"(r) : "f"(a)); return r;
}
__device__ __forceinline__ void unpack2(float& lo, float& hi, ull v) {
    asm("mov.b64 {%0, %1}, %2;" : "=f"(lo), "=f"(hi) : "l"(v));
}
#define FFMA2(d, a, b) asm("fma.rn.f32x2 %0, %1, %2, %0;" : "+l"(d) : "l"(a), "l"(b))

// ---------------- warp-MMA helpers (sm_80+ path; no 'a'-gated instructions) ------
__device__ __forceinline__ uint32_t smem_u32(const void* p) {
    return (uint32_t)__cvta_generic_to_shared(p);
}
__device__ __forceinline__ void mma_bf16(float* c, const uint32_t* a, const uint32_t* b) {
    asm volatile(
        "mma.sync.aligned.m16n8k16.row.col.f32.bf16.bf16.f32 "
        "{%0,%1,%2,%3}, {%4,%5,%6,%7}, {%8,%9}, {%0,%1,%2,%3};"
        : "+f"(c[0]), "+f"(c[1]), "+f"(c[2]), "+f"(c[3])
        : "r"(a[0]), "r"(a[1]), "r"(a[2]), "r"(a[3]), "r"(b[0]), "r"(b[1]));
}
__device__ __forceinline__ void ldm_x4(uint32_t* r, uint32_t addr) {
    asm volatile("ldmatrix.sync.aligned.m8n8.x4.shared.b16 {%0,%1,%2,%3}, [%4];"
        : "=r"(r[0]), "=r"(r[1]), "=r"(r[2]), "=r"(r[3]) : "r"(addr));
}
__device__ __forceinline__ void cp16(uint32_t dst, const void* src, int sz) {
    asm volatile("cp.async.cg.shared.global [%0], [%1], 16, %2;"
        :: "r"(dst), "l"(src), "r"(sz));
}
#define CP_COMMIT() asm volatile("cp.async.commit_group;" ::: "memory")
#define CP_WAIT(N)  asm volatile("cp.async.wait_group %0;" :: "n"(N) : "memory")

// =====================================================================
// Kernel 0: weight pre-split: OIHW fp32 -> [(kh3+kw)*256+n][c] bf16 hi/lo
// =====================================================================
__global__ __launch_bounds__(256)
void wconv_kernel(const float* __restrict__ w, __nv_bfloat16* __restrict__ oh,
                  __nv_bfloat16* __restrict__ ol) {
    int idx = blockIdx.x * 256 + threadIdx.x;  // = (j*256 + n)*256 + c
    int c = idx & 255;
    int n = (idx >> 8) & 255;
    int j = idx >> 16;
    float v = w[((n << 8) + c) * 9 + j];
    __nv_bfloat16 hi = __float2bfloat16_rn(v);
    oh[idx] = hi;
    ol[idx] = __float2bfloat16_rn(v - __bfloat162float(hi));
}

// =====================================================================
// Kernel 1: weighted fusion (FFMA2 GEMM) -> HWC output
// =====================================================================
__global__ __launch_bounds__(256)
void fusion_kernel(const float* __restrict__ f1, const float* __restrict__ f2,
                   const float* __restrict__ f3, const float* __restrict__ f4,
                   const float* __restrict__ pw, const float* __restrict__ lwr,
                   float* __restrict__ out) {
    __shared__ float As[16][64];
    __shared__ float Bs[16][64];
    const float* fs[4] = {f1, f2, f3, f4};

    float l0 = __ldg(lwr), l1 = __ldg(lwr+1), l2 = __ldg(lwr+2), l3 = __ldg(lwr+3);
    float mx = fmaxf(fmaxf(l0,l1), fmaxf(l2,l3));
    float e0 = expf(l0-mx), e1 = expf(l1-mx), e2 = expf(l2-mx), e3 = expf(l3-mx);
    float inv = 1.0f/(e0+e1+e2+e3);
    float lw[4] = {e0*inv, e1*inv, e2*inv, e3*inv};

    int tid = threadIdx.x;
    int tx = tid & 15, ty = tid >> 4;
    int m0 = blockIdx.x * 64;
    int fo0 = blockIdx.y * 64;
    int b  = m0 >> 10;
    int nb = m0 & 1023;
    int lm = tid & 63;
    int lk = tid >> 6;

    float outacc[4][4];
    #pragma unroll
    for (int i=0;i<4;i++)
        #pragma unroll
        for (int j=0;j<4;j++) outacc[i][j]=0.f;

    #pragma unroll
    for (int l = 0; l < 4; l++) {
        const float* A  = fs[l] + b * CIN * N0 + nb;
        const float* Wl = pw + l * CIN * FC + fo0;
        ull acc2[4][2];
        #pragma unroll
        for (int i=0;i<4;i++) { acc2[i][0]=0ULL; acc2[i][1]=0ULL; }

        for (int k0 = 0; k0 < CIN; k0 += 16) {
            #pragma unroll
            for (int i = 0; i < 4; i++) {
                int kk = lk + i*4;
                As[kk][lm] = A [(k0+kk)*N0 + lm];
                Bs[kk][lm] = Wl[(k0+kk)*FC + lm];
            }
            __syncthreads();
            #pragma unroll
            for (int kk = 0; kk < 16; kk++) {
                float4 av = *(const float4*)&As[kk][tx*4];
                ulonglong2 bq = *(const ulonglong2*)&Bs[kk][ty*4];
                ull ad[4] = {pack_dup(av.x), pack_dup(av.y),
                             pack_dup(av.z), pack_dup(av.w)};
                #pragma unroll
                for (int i=0;i<4;i++) {
                    FFMA2(acc2[i][0], ad[i], bq.x);
                    FFMA2(acc2[i][1], ad[i], bq.y);
                }
            }
            __syncthreads();
        }
        float wl = lw[l];
        #pragma unroll
        for (int i=0;i<4;i++)
            #pragma unroll
            for (int jp=0;jp<2;jp++) {
                float vlo, vhi;
                unpack2(vlo, vhi, acc2[i][jp]);
                outacc[i][2*jp+0] = fmaf(wl, gelu_exact(vlo), outacc[i][2*jp+0]);
                outacc[i][2*jp+1] = fmaf(wl, gelu_exact(vhi), outacc[i][2*jp+1]);
            }
    }
    // HWC write: out[(b*1024 + spatial)*256 + f], contiguous in f
    #pragma unroll
    for (int i = 0; i < 4; i++) {
        int sp = nb + tx*4 + i;
        float4 v = make_float4(outacc[i][0], outacc[i][1], outacc[i][2], outacc[i][3]);
        *(float4*)&out[((size_t)b*N0 + sp)*FC + fo0 + ty*4] = v;
    }
}

// =====================================================================
// Kernel 2: depthwise 3x3 + BN + residual ReLU (HWC, 32x32)
// =====================================================================
__global__ __launch_bounds__(256)
void enhance_kernel(const float* __restrict__ x, const float* __restrict__ dw,
                    const float* __restrict__ bnp, float* __restrict__ out) {
    __shared__ float dws[FC*9];
    __shared__ float bsc[FC], bsh[FC];
    int tid = threadIdx.x;
    for (int i = tid; i < FC*9; i += 256) dws[i] = dw[i];
    {
        float g = bnp[tid], be = bnp[256+tid], mu = bnp[512+tid], va = bnp[768+tid];
        float sc = g * rsqrtf(va + 1e-5f);
        bsc[tid] = sc; bsh[tid] = be - mu*sc;
    }
    __syncthreads();
    int idx = blockIdx.x * 256 + tid;          // (b*1024 + s)*256 + c
    int c = idx & 255;
    int sp = idx >> 8;
    int s = sp & 1023;
    int w = s & 31, h = s >> 5;
    float xc = x[idx];
    float y = 0.f;
    #pragma unroll
    for (int kh = 0; kh < 3; kh++) {
        int iy = h + kh - 1;
        if ((unsigned)iy < 32u) {
            #pragma unroll
            for (int kw = 0; kw < 3; kw++) {
                int ix = w + kw - 1;
                if ((unsigned)ix < 32u)
                    y = fmaf(dws[c*9 + kh*3 + kw],
                             x[((sp - s) + (iy<<5) + ix)*FC + c], y);
            }
        }
    }
    out[idx] = fmaxf(fmaf(y, bsc[c], bsh[c]) + xc, 0.f);
}

// =====================================================================
// Kernel 3: 1x1 offset conv (HWC in, 256 -> 32) + bias
// =====================================================================
__global__ __launch_bounds__(256)
void offset_kernel(const float* __restrict__ in, const float* __restrict__ ow,
                   const float* __restrict__ ob, float* __restrict__ off,
                   int H, int W) {
    int HW = H*W;
    int idx = blockIdx.x*256 + threadIdx.x;   // B*32*HW
    int s  = idx % HW;
    int ch = (idx / HW) & 31;
    int b  = idx / (32*HW);
    const float4* ip = (const float4*)(in + ((size_t)b*HW + s)*FC);
    const float4* wp = (const float4*)(ow + ch*FC);
    float acc = __ldg(&ob[ch]);
    #pragma unroll 8
    for (int c = 0; c < 64; c++) {
        float4 a = ip[c], w4 = wp[c];
        acc = fmaf(a.x, w4.x, acc); acc = fmaf(a.y, w4.y, acc);
        acc = fmaf(a.z, w4.z, acc); acc = fmaf(a.w, w4.w, acc);
    }
    off[idx] = acc;
}

// =====================================================================
// Kernel 4: DySample bilinear gather (HWC in fp32, HWC out bf16 hi/lo)
// =====================================================================
__global__ __launch_bounds__(256)
void upsample_kernel(const float* __restrict__ x, const float* __restrict__ off,
                     __nv_bfloat16* __restrict__ oh, __nv_bfloat16* __restrict__ ol,
                     int H, int W) {
    int W2 = 2*W, H2 = 2*H, HW = H*W;
    int idx = blockIdx.x*256 + threadIdx.x;   // ((b*H2+ho)*W2+wo)*256 + c
    int c  = idx & 255;
    int sp = idx >> 8;
    int wo = sp % W2;
    int t  = sp / W2;
    int ho = t % H2;
    int b  = t / H2;
    int g  = c >> 6;
    int h = ho >> 1, dh = ho & 1, w = wo >> 1, dw = wo & 1;
    int obase = ((b*32 + g*4 + dh*2 + dw)*H + h)*W + w;
    float offx = off[obase]         * 0.25f + (0.5f*(float)dw - 0.25f);
    float offy = off[obase + 16*HW] * 0.25f + (0.5f*(float)dh - 0.25f);
    float px = fminf(fmaxf((float)w + offx, 0.f), (float)(W-1));
    float py = fminf(fmaxf((float)h + offy, 0.f), (float)(H-1));
    int x0 = (int)px;
    int y0 = (int)py;
    float wx = px - (float)x0, wy = py - (float)y0;
    int x1 = min(x0+1, W-1);
    int y1 = min(y0+1, H-1);
    const float* ib = x + (size_t)b*HW*FC + c;
    float v00 = ib[((size_t)y0*W + x0)*FC], v01 = ib[((size_t)y0*W + x1)*FC];
    float v10 = ib[((size_t)y1*W + x0)*FC], v11 = ib[((size_t)y1*W + x1)*FC];
    float v0 = v00 + (v01 - v00)*wx;
    float v1 = v10 + (v11 - v10)*wx;
    float v  = v0 + (v1 - v0)*wy;
    __nv_bfloat16 hi = __float2bfloat16_rn(v);
    oh[idx] = hi;
    ol[idx] = __float2bfloat16_rn(v - __bfloat162float(hi));
}

// =====================================================================
// Kernel 5: 3x3 conv 256->256, warp-MMA bf16-split implicit GEMM + BN + ReLU.
// CTA tile 128(M spatial) x 128(N chans), K = 9 taps x 256 ch as 36 chunks of 64.
// Split: D += Ah*Bh + Ah*Bl + Al*Bh. cp.async double-buffered SMEM.
// SMEM: [0,1KB) bn scale | [1KB,2KB) bn shift | [2KB +) 2 bufs x 4 planes.
// Plane = 128 rows x 144B (64 bf16 + 16B pad -> conflict-free ldmatrix).
// 8 warps as 4(M) x 2(N): warp tile 32 x 64; 48 HMMA per k16.
// =====================================================================
#define PS 18432                 // plane stride: 128*144
#define BUFSZ (4*PS)             // Ah, Al, Bh, Bl
#define CONV_SMEM (2048 + 2*BUFSZ)   // 149504 bytes

#define LOAD_CHUNK(ci, buf)                                                     \
    do {                                                                        \
        int kh_ = (ci)/12, rem_ = (ci) - kh_*12;                                \
        int kw_ = rem_ >> 2, cc_ = (rem_ & 3) << 6;                             \
        int yy_ = y + kh_ - 1, xx_ = x + kw_ - 1;                               \
        bool val_ = ((unsigned)yy_ < (unsigned)H) && ((unsigned)xx_ < (unsigned)W); \
        int vsz_ = val_ ? 16 : 0;                                               \
        long ao_ = ((long)(b*H + (val_?yy_:0))*W + (val_?xx_:0))*FC + cc_ + sbase*8; \
        uint32_t ab_ = sb + 2048u + (uint32_t)(buf)*BUFSZ + lr*144 + sbase*16;  \
        const __nv_bfloat16* ah_ = inh + ao_;                                   \
        const __nv_bfloat16* al_ = inl + ao_;                                   \
        _Pragma("unroll")                                                       \
        for (int j_ = 0; j_ < 4; j_++) {                                        \
            cp16(ab_ + j_*16,      ah_ + j_*8, vsz_);                           \
            cp16(ab_ + PS + j_*16, al_ + j_*8, vsz_);                           \
        }                                                                       \
        long bo_ = ((long)((kh_*3+kw_)*FC + n0c + lr))*FC + cc_ + sbase*8;      \
        const __nv_bfloat16* bh_ = wh + bo_;                                    \
        const __nv_bfloat16* bl_ = wl + bo_;                                    \
        uint32_t bb_ = ab_ + 2*PS;                                              \
        _Pragma("unroll")                                                       \
        for (int j_ = 0; j_ < 4; j_++) {                                        \
            cp16(bb_ + j_*16,      bh_ + j_*8, 16);                             \
            cp16(bb_ + PS + j_*16, bl_ + j_*8, 16);                             \
        }                                                                       \
    } while (0)

__global__ __launch_bounds__(256, 1)
void conv_mma(const __nv_bfloat16* __restrict__ inh, const __nv_bfloat16* __restrict__ inl,
              const __nv_bfloat16* __restrict__ wh,  const __nv_bfloat16* __restrict__ wl,
              const float* __restrict__ bnp, float* __restrict__ out, int H, int W) {
    extern __shared__ char sm[];
    float* bsc = (float*)sm;
    float* bshf = (float*)(sm + 1024);
    uint32_t sb = smem_u32(sm);
    int tid = threadIdx.x;
    int lane = tid & 31, wid = tid >> 5;
    const int HW = H*W;
    int m0 = blockIdx.x * 128;
    int n0c = blockIdx.y * 128;

    {
        float g = bnp[tid], be = bnp[256+tid], mu = bnp[512+tid], va = bnp[768+tid];
        float sc = g * rsqrtf(va + 1e-5f);
        bsc[tid] = sc; bshf[tid] = be - mu*sc;
    }

    // per-thread load geometry: row lr (0..127), two threads per row
    int lr = tid >> 1;
    int sbase = (tid & 1) * 4;     // 16B-seg base (0 or 4)
    int mrow = m0 + lr;
    int b = mrow / HW;
    int s = mrow - b*HW;
    int y = s / W, x = s - y*W;

    // warp compute geometry
    int wm = wid & 3;              // 4 warps in M (32 rows each)
    int wn = wid >> 2;             // 2 warps in N (64 cols each)
    int alr = lane & 15;
    int alc = (lane >> 4) << 4;    // 0 or 16 bytes
    int bg = lane >> 3;
    int brow_off = ((bg >> 1) << 3) + (lane & 7);
    int bcol = (bg & 1) << 4;

    float acc[2][8][4];
    #pragma unroll
    for (int i=0;i<2;i++)
        #pragma unroll
        for (int j=0;j<8;j++)
            #pragma unroll
            for (int k=0;k<4;k++) acc[i][j][k]=0.f;

    LOAD_CHUNK(0, 0);
    CP_COMMIT();

    for (int ci = 0; ci < 36; ci++) {
        int buf = ci & 1;
        if (ci < 35) {
            LOAD_CHUNK(ci+1, (ci+1)&1);
            CP_COMMIT();
            CP_WAIT(1);
        } else {
            CP_WAIT(0);
        }
        __syncthreads();

        uint32_t base = sb + 2048u + (uint32_t)buf*BUFSZ;
        #pragma unroll
        for (int k16 = 0; k16 < 4; k16++) {
            uint32_t ah4[2][4], al4[2][4];
            uint32_t bh2[8][2], bl2[8][2];
            #pragma unroll
            for (int mt = 0; mt < 2; mt++) {
                uint32_t aaddr = base + (uint32_t)((wm*32 + mt*16 + alr)*144 + k16*32 + alc);
                ldm_x4(ah4[mt], aaddr);
                ldm_x4(al4[mt], aaddr + PS);
            }
            #pragma unroll
            for (int np = 0; np < 4; np++) {
                uint32_t baddr = base + 2*PS +
                    (uint32_t)((wn*64 + np*16 + brow_off)*144 + k16*32 + bcol);
                uint32_t t4[4];
                ldm_x4(t4, baddr);
                bh2[np*2][0]=t4[0]; bh2[np*2][1]=t4[1];
                bh2[np*2+1][0]=t4[2]; bh2[np*2+1][1]=t4[3];
                ldm_x4(t4, baddr + PS);
                bl2[np*2][0]=t4[0]; bl2[np*2][1]=t4[1];
                bl2[np*2+1][0]=t4[2]; bl2[np*2+1][1]=t4[3];
            }
            #pragma unroll
            for (int mt = 0; mt < 2; mt++)
                #pragma unroll
                for (int nt = 0; nt < 8; nt++) {
                    mma_bf16(acc[mt][nt], ah4[mt], bh2[nt]);
                    mma_bf16(acc[mt][nt], ah4[mt], bl2[nt]);
                    mma_bf16(acc[mt][nt], al4[mt], bh2[nt]);
                }
        }
        __syncthreads();
    }

    // epilogue: BN + ReLU, HWC float2 stores
    #pragma unroll
    for (int mt = 0; mt < 2; mt++) {
        int rbase = m0 + wm*32 + mt*16 + (lane >> 2);
        #pragma unroll
        for (int h2 = 0; h2 < 2; h2++) {
            int mr = rbase + h2*8;
            int bb2 = mr / HW;
            int ss  = mr - bb2*HW;
            float* op = out + ((size_t)bb2*HW + ss)*FC;
            #pragma unroll
            for (int nt = 0; nt < 8; nt++) {
                int n = n0c + wn*64 + nt*8 + (lane & 3)*2;
                float2 v;
                v.x = fmaxf(fmaf(acc[mt][nt][h2*2+0], bsc[n],   bshf[n]),   0.f);
                v.y = fmaxf(fmaf(acc[mt][nt][h2*2+1], bsc[n+1], bshf[n+1]), 0.f);
                *(float2*)(op + n) = v;
            }
        }
    }
}

// =====================================================================
// Kernel 6: head conv 3x3, 256 -> 1, + bias (HWC in)
// =====================================================================
__global__ __launch_bounds__(256)
void outconv_kernel(const float* __restrict__ in, const float* __restrict__ wv,
                    const float* __restrict__ bias, float* __restrict__ out,
                    int H, int W) {
    __shared__ float ws2[9*FC];   // [j][c]
    int tid = threadIdx.x;
    for (int i = tid; i < 9*FC; i += 256) {
        int j = i >> 8, c = i & 255;
        ws2[i] = wv[c*9 + j];
    }
    __syncthreads();
    int HW = H*W;
    int idx = blockIdx.x*256 + tid;
    int s = idx % HW;
    int b = idx / HW;
    int y = s / W, x = s % W;
    float acc = __ldg(bias);
    #pragma unroll
    for (int kh = 0; kh < 3; kh++) {
        int iy = y + kh - 1;
        if ((unsigned)iy >= (unsigned)H) continue;
        #pragma unroll
        for (int kw = 0; kw < 3; kw++) {
            int ix = x + kw - 1;
            if ((unsigned)ix >= (unsigned)W) continue;
            const float4* ip = (const float4*)(in + ((size_t)(b*H + iy)*W + ix)*FC);
            const float4* wp = (const float4*)(ws2 + (kh*3 + kw)*FC);
            #pragma unroll 8
            for (int c = 0; c < 64; c++) {
                float4 a = ip[c], w4 = wp[c];
                acc = fmaf(a.x, w4.x, acc); acc = fmaf(a.y, w4.y, acc);
                acc = fmaf(a.z, w4.z, acc); acc = fmaf(a.w, w4.w, acc);
            }
        }
    }
    out[idx] = acc;
}

// =====================================================================
// launcher
// =====================================================================
extern "C" void kernel_launch(void* const* d_in, const int* in_sizes, int n_in,
                              void* d_out, int out_size) {
    const float* f1  = (const float*)d_in[0];
    const float* f2  = (const float*)d_in[1];
    const float* f3  = (const float*)d_in[2];
    const float* f4  = (const float*)d_in[3];
    const float* pw  = (const float*)d_in[4];
    const float* lw  = (const float*)d_in[5];
    const float* dww = (const float*)d_in[6];
    const float* bne = (const float*)d_in[7];
    const float* ow1 = (const float*)d_in[8];
    const float* ob1 = (const float*)d_in[9];
    const float* cw1 = (const float*)d_in[10];
    const float* bn1 = (const float*)d_in[11];
    const float* ow2 = (const float*)d_in[12];
    const float* ob2 = (const float*)d_in[13];
    const float* cw2 = (const float*)d_in[14];
    const float* bn2 = (const float*)d_in[15];
    const float* owv = (const float*)d_in[16];
    const float* obv = (const float*)d_in[17];
    float* outp = (float*)d_out;

    float *px0, *penh, *poff, *pc1, *pc2;
    __nv_bfloat16 *puh, *pul, *pw1h, *pw1l, *pw2h, *pw2l;
    cudaGetSymbolAddress((void**)&px0,  g_x0t);
    cudaGetSymbolAddress((void**)&penh, g_enht);
    cudaGetSymbolAddress((void**)&poff, g_off);
    cudaGetSymbolAddress((void**)&puh,  g_uph);
    cudaGetSymbolAddress((void**)&pul,  g_upl);
    cudaGetSymbolAddress((void**)&pc1,  g_c1t);
    cudaGetSymbolAddress((void**)&pc2,  g_c2t);
    cudaGetSymbolAddress((void**)&pw1h, g_w1h);
    cudaGetSymbolAddress((void**)&pw1l, g_w1l);
    cudaGetSymbolAddress((void**)&pw2h, g_w2h);
    cudaGetSymbolAddress((void**)&pw2l, g_w2l);

    cudaFuncSetAttribute(conv_mma, cudaFuncAttributeMaxDynamicSharedMemorySize, CONV_SMEM);

    // 0) pre-split conv weights to bf16 hi/lo
    wconv_kernel<<<2304, 256>>>(cw1, pw1h, pw1l);
    wconv_kernel<<<2304, 256>>>(cw2, pw2h, pw2l);
    // 1) weighted fusion GEMM + GELU -> HWC (B,32,32,256)
    fusion_kernel<<<dim3(64, 4), 256>>>(f1, f2, f3, f4, pw, lw, px0);
    // 2) depthwise enhancer (HWC)
    enhance_kernel<<<4096, 256>>>(px0, dww, bne, penh);
    // 3) stage 1: offsets, upsample to 64x64 (bf16 hi/lo), warp-MMA conv
    offset_kernel  <<<512,   256>>>(penh, ow1, ob1, poff, 32, 32);
    upsample_kernel<<<16384, 256>>>(penh, poff, puh, pul, 32, 32);
    conv_mma<<<dim3(128, 2), 256, CONV_SMEM>>>(puh, pul, pw1h, pw1l, bn1, pc1, 64, 64);
    // 4) stage 2: offsets, upsample to 128x128, warp-MMA conv
    offset_kernel  <<<2048,  256>>>(pc1, ow2, ob2, poff, 64, 64);
    upsample_kernel<<<65536, 256>>>(pc1, poff, puh, pul, 64, 64);
    conv_mma<<<dim3(512, 2), 256, CONV_SMEM>>>(puh, pul, pw2h, pw2l, bn2, pc2, 128, 128);
    // 5) depth head (HWC reduction)
    outconv_kernel <<<256, 256>>>(pc2, owv, obv, outp, 128, 128);
}

// round 14
// speedup vs baseline: 1.7385x; 1.0014x over previous
#include <cuda_runtime.h>
#include <cuda_bf16.h>
#include <math.h>
#include <stdint.h>

// ---------------- problem constants ----------------
#define BN  4
#define CIN 768
#define FC  256
#define N0  1024   // 32*32

// ---------------- scratch (device globals; no allocations allowed) ----------------
// HWC layouts: [(b*H + y)*W + x][c]
__device__ float g_x0t [BN*N0*FC];                 //  4 MB fusion out (HWC, 32x32)
__device__ float g_enht[BN*N0*FC];                 //  4 MB enhanced   (HWC, 32x32)
__device__ float g_off [BN*32*64*64];              //  2 MB offsets (NCHW, max stage-2)
__device__ __nv_bfloat16 g_uph[BN*128*128*FC];     // 33.5 MB upsampled hi (HWC bf16)
__device__ __nv_bfloat16 g_upl[BN*128*128*FC];     // 33.5 MB upsampled lo
__device__ float g_c1t [BN*64*64*FC];              // 16 MB conv1 out (HWC)
__device__ float g_c2t [BN*128*128*FC];            // 64 MB conv2 out (HWC)
// pre-split conv weights: [(kh*3+kw)*256 + n][c] bf16
__device__ __nv_bfloat16 g_w1h[9*FC*FC], g_w1l[9*FC*FC];
__device__ __nv_bfloat16 g_w2h[9*FC*FC], g_w2l[9*FC*FC];

__device__ __forceinline__ float gelu_exact(float x) {
    return 0.5f * x * (1.0f + erff(x * 0.70710678118654752440f));
}

// ---------------- packed fp32x2 helpers (fusion kernel) ----------------
typedef unsigned long long ull;
__device__ __forceinline__ ull pack_dup(float a) {
    ull r; asm("mov.b64 %0, {%1, %1};" : "=l"(r) : "f"(a)); return r;
}
__device__ __forceinline__ void unpack2(float& lo, float& hi, ull v) {
    asm("mov.b64 {%0, %1}, %2;" : "=f"(lo), "=f"(hi) : "l"(v));
}
#define FFMA2(d, a, b) asm("fma.rn.f32x2 %0, %1, %2, %0;" : "+l"(d) : "l"(a), "l"(b))

// ---------------- warp-MMA helpers (sm_80+ path; no 'a'-gated instructions) ------
__device__ __forceinline__ uint32_t smem_u32(const void* p) {
    return (uint32_t)__cvta_generic_to_shared(p);
}
__device__ __forceinline__ void mma_bf16(float* c, const uint32_t* a, const uint32_t* b) {
    asm volatile(
        "mma.sync.aligned.m16n8k16.row.col.f32.bf16.bf16.f32 "
        "{%0,%1,%2,%3}, {%4,%5,%6,%7}, {%8,%9}, {%0,%1,%2,%3};"
        : "+f"(c[0]), "+f"(c[1]), "+f"(c[2]), "+f"(c[3])
        : "r"(a[0]), "r"(a[1]), "r"(a[2]), "r"(a[3]), "r"(b[0]), "r"(b[1]));
}
__device__ __forceinline__ void ldm_x4(uint32_t* r, uint32_t addr) {
    asm volatile("ldmatrix.sync.aligned.m8n8.x4.shared.b16 {%0,%1,%2,%3}, [%4];"
        : "=r"(r[0]), "=r"(r[1]), "=r"(r[2]), "=r"(r[3]) : "r"(addr));
}
__device__ __forceinline__ void cp16(uint32_t dst, const void* src, int sz) {
    asm volatile("cp.async.cg.shared.global [%0], [%1], 16, %2;"
        :: "r"(dst), "l"(src), "r"(sz));
}
#define CP_COMMIT() asm volatile("cp.async.commit_group;" ::: "memory")
#define CP_WAIT(N)  asm volatile("cp.async.wait_group %0;" :: "n"(N) : "memory")

// =====================================================================
// Kernel 0: weight pre-split: OIHW fp32 -> [(kh3+kw)*256+n][c] bf16 hi/lo
// =====================================================================
__global__ __launch_bounds__(256)
void wconv_kernel(const float* __restrict__ w, __nv_bfloat16* __restrict__ oh,
                  __nv_bfloat16* __restrict__ ol) {
    int idx = blockIdx.x * 256 + threadIdx.x;  // = (j*256 + n)*256 + c
    int c = idx & 255;
    int n = (idx >> 8) & 255;
    int j = idx >> 16;
    float v = w[((n << 8) + c) * 9 + j];
    __nv_bfloat16 hi = __float2bfloat16_rn(v);
    oh[idx] = hi;
    ol[idx] = __float2bfloat16_rn(v - __bfloat162float(hi));
}

// =====================================================================
// Kernel 1: weighted fusion (FFMA2 GEMM) -> HWC output
// =====================================================================
__global__ __launch_bounds__(256)
void fusion_kernel(const float* __restrict__ f1, const float* __restrict__ f2,
                   const float* __restrict__ f3, const float* __restrict__ f4,
                   const float* __restrict__ pw, const float* __restrict__ lwr,
                   float* __restrict__ out) {
    __shared__ float As[16][64];
    __shared__ float Bs[16][64];
    const float* fs[4] = {f1, f2, f3, f4};

    float l0 = __ldg(lwr), l1 = __ldg(lwr+1), l2 = __ldg(lwr+2), l3 = __ldg(lwr+3);
    float mx = fmaxf(fmaxf(l0,l1), fmaxf(l2,l3));
    float e0 = expf(l0-mx), e1 = expf(l1-mx), e2 = expf(l2-mx), e3 = expf(l3-mx);
    float inv = 1.0f/(e0+e1+e2+e3);
    float lw[4] = {e0*inv, e1*inv, e2*inv, e3*inv};

    int tid = threadIdx.x;
    int tx = tid & 15, ty = tid >> 4;
    int m0 = blockIdx.x * 64;
    int fo0 = blockIdx.y * 64;
    int b  = m0 >> 10;
    int nb = m0 & 1023;
    int lm = tid & 63;
    int lk = tid >> 6;

    float outacc[4][4];
    #pragma unroll
    for (int i=0;i<4;i++)
        #pragma unroll
        for (int j=0;j<4;j++) outacc[i][j]=0.f;

    #pragma unroll
    for (int l = 0; l < 4; l++) {
        const float* A  = fs[l] + b * CIN * N0 + nb;
        const float* Wl = pw + l * CIN * FC + fo0;
        ull acc2[4][2];
        #pragma unroll
        for (int i=0;i<4;i++) { acc2[i][0]=0ULL; acc2[i][1]=0ULL; }

        for (int k0 = 0; k0 < CIN; k0 += 16) {
            #pragma unroll
            for (int i = 0; i < 4; i++) {
                int kk = lk + i*4;
                As[kk][lm] = A [(k0+kk)*N0 + lm];
                Bs[kk][lm] = Wl[(k0+kk)*FC + lm];
            }
            __syncthreads();
            #pragma unroll
            for (int kk = 0; kk < 16; kk++) {
                float4 av = *(const float4*)&As[kk][tx*4];
                ulonglong2 bq = *(const ulonglong2*)&Bs[kk][ty*4];
                ull ad[4] = {pack_dup(av.x), pack_dup(av.y),
                             pack_dup(av.z), pack_dup(av.w)};
                #pragma unroll
                for (int i=0;i<4;i++) {
                    FFMA2(acc2[i][0], ad[i], bq.x);
                    FFMA2(acc2[i][1], ad[i], bq.y);
                }
            }
            __syncthreads();
        }
        float wl = lw[l];
        #pragma unroll
        for (int i=0;i<4;i++)
            #pragma unroll
            for (int jp=0;jp<2;jp++) {
                float vlo, vhi;
                unpack2(vlo, vhi, acc2[i][jp]);
                outacc[i][2*jp+0] = fmaf(wl, gelu_exact(vlo), outacc[i][2*jp+0]);
                outacc[i][2*jp+1] = fmaf(wl, gelu_exact(vhi), outacc[i][2*jp+1]);
            }
    }
    // HWC write: out[(b*1024 + spatial)*256 + f], contiguous in f
    #pragma unroll
    for (int i = 0; i < 4; i++) {
        int sp = nb + tx*4 + i;
        float4 v = make_float4(outacc[i][0], outacc[i][1], outacc[i][2], outacc[i][3]);
        *(float4*)&out[((size_t)b*N0 + sp)*FC + fo0 + ty*4] = v;
    }
}

// =====================================================================
// Kernel 2: depthwise 3x3 + BN + residual ReLU (HWC, 32x32)
// =====================================================================
__global__ __launch_bounds__(256)
void enhance_kernel(const float* __restrict__ x, const float* __restrict__ dw,
                    const float* __restrict__ bnp, float* __restrict__ out) {
    __shared__ float dws[FC*9];
    __shared__ float bsc[FC], bsh[FC];
    int tid = threadIdx.x;
    for (int i = tid; i < FC*9; i += 256) dws[i] = dw[i];
    {
        float g = bnp[tid], be = bnp[256+tid], mu = bnp[512+tid], va = bnp[768+tid];
        float sc = g * rsqrtf(va + 1e-5f);
        bsc[tid] = sc; bsh[tid] = be - mu*sc;
    }
    __syncthreads();
    int idx = blockIdx.x * 256 + tid;          // (b*1024 + s)*256 + c
    int c = idx & 255;
    int sp = idx >> 8;
    int s = sp & 1023;
    int w = s & 31, h = s >> 5;
    float xc = x[idx];
    float y = 0.f;
    #pragma unroll
    for (int kh = 0; kh < 3; kh++) {
        int iy = h + kh - 1;
        if ((unsigned)iy < 32u) {
            #pragma unroll
            for (int kw = 0; kw < 3; kw++) {
                int ix = w + kw - 1;
                if ((unsigned)ix < 32u)
                    y = fmaf(dws[c*9 + kh*3 + kw],
                             x[((sp - s) + (iy<<5) + ix)*FC + c], y);
            }
        }
    }
    out[idx] = fmaxf(fmaf(y, bsc[c], bsh[c]) + xc, 0.f);
}

// =====================================================================
// Kernel 3: 1x1 offset conv (HWC in, 256 -> 32) + bias.
// Warp-per-pixel: lane = out-channel, uniform (broadcast) pixel loads,
// SMEM-transposed weights [c][j] -> conflict-free LDS. 32x less L2 read
// traffic than thread-per-(ch,pixel).
// =====================================================================
__global__ __launch_bounds__(256)
void offset_kernel(const float* __restrict__ in, const float* __restrict__ ow,
                   const float* __restrict__ ob, float* __restrict__ off,
                   int H, int W) {
    __shared__ float ws[FC*32];   // [c][j]
    int tid = threadIdx.x;
    for (int i = tid; i < FC*32; i += 256) {
        int c = i >> 5, j = i & 31;
        ws[i] = ow[j*FC + c];
    }
    __syncthreads();
    int HW = H*W;
    int wid = tid >> 5, j = tid & 31;
    int p = blockIdx.x * 8 + wid;              // pixel in [0, BN*HW)
    const float4* ip = (const float4*)(in + (size_t)p*FC);
    float acc = __ldg(&ob[j]);
    #pragma unroll 4
    for (int c4 = 0; c4 < 64; c4++) {
        float4 v = ip[c4];                     // uniform across warp -> broadcast
        int c = c4 * 4;
        acc = fmaf(v.x, ws[(c+0)*32 + j], acc);
        acc = fmaf(v.y, ws[(c+1)*32 + j], acc);
        acc = fmaf(v.z, ws[(c+2)*32 + j], acc);
        acc = fmaf(v.w, ws[(c+3)*32 + j], acc);
    }
    int b = p / HW, s = p - b*HW;
    off[(b*32 + j)*HW + s] = acc;
}

// =====================================================================
// Kernel 4: DySample bilinear gather (HWC in fp32, HWC out bf16 hi/lo)
// =====================================================================
__global__ __launch_bounds__(256)
void upsample_kernel(const float* __restrict__ x, const float* __restrict__ off,
                     __nv_bfloat16* __restrict__ oh, __nv_bfloat16* __restrict__ ol,
                     int H, int W) {
    int W2 = 2*W, H2 = 2*H, HW = H*W;
    int idx = blockIdx.x*256 + threadIdx.x;   // ((b*H2+ho)*W2+wo)*256 + c
    int c  = idx & 255;
    int sp = idx >> 8;
    int wo = sp % W2;
    int t  = sp / W2;
    int ho = t % H2;
    int b  = t / H2;
    int g  = c >> 6;
    int h = ho >> 1, dh = ho & 1, w = wo >> 1, dw = wo & 1;
    int obase = ((b*32 + g*4 + dh*2 + dw)*H + h)*W + w;
    float offx = off[obase]         * 0.25f + (0.5f*(float)dw - 0.25f);
    float offy = off[obase + 16*HW] * 0.25f + (0.5f*(float)dh - 0.25f);
    float px = fminf(fmaxf((float)w + offx, 0.f), (float)(W-1));
    float py = fminf(fmaxf((float)h + offy, 0.f), (float)(H-1));
    int x0 = (int)px;
    int y0 = (int)py;
    float wx = px - (float)x0, wy = py - (float)y0;
    int x1 = min(x0+1, W-1);
    int y1 = min(y0+1, H-1);
    const float* ib = x + (size_t)b*HW*FC + c;
    float v00 = ib[((size_t)y0*W + x0)*FC], v01 = ib[((size_t)y0*W + x1)*FC];
    float v10 = ib[((size_t)y1*W + x0)*FC], v11 = ib[((size_t)y1*W + x1)*FC];
    float v0 = v00 + (v01 - v00)*wx;
    float v1 = v10 + (v11 - v10)*wx;
    float v  = v0 + (v1 - v0)*wy;
    __nv_bfloat16 hi = __float2bfloat16_rn(v);
    oh[idx] = hi;
    ol[idx] = __float2bfloat16_rn(v - __bfloat162float(hi));
}

// =====================================================================
// Kernel 5: 3x3 conv 256->256, warp-MMA bf16-split implicit GEMM + BN + ReLU.
// v2: CTA tile 128(M) x 256(N full), 8 warps as 2(M)x4(N), warp tile 64x64.
// Cuts inter-warp LDSM duplication by 33% per output and halves A traffic.
// K = 9 taps x 256 ch as 36 chunks of 64. Split: D += Ah*Bh + Ah*Bl + Al*Bh.
// SMEM: [0,1KB) bn scale | [1KB,2KB) bn shift | 2 bufs x (Ah,Al: 128x144B;
// Bh,Bl: 256x144B) = 223232 B total.
// =====================================================================
#define APS 18432                    // A plane: 128*144
#define BPS 36864                    // B plane: 256*144
#define BUFSZ (2*APS + 2*BPS)        // 110592
#define CONV_SMEM (2048 + 2*BUFSZ)   // 223232

#define LOAD_CHUNK(ci, buf)                                                     \
    do {                                                                        \
        int kh_ = (ci)/12, rem_ = (ci) - kh_*12;                                \
        int kw_ = rem_ >> 2, cc_ = (rem_ & 3) << 6;                             \
        int yy_ = y + kh_ - 1, xx_ = x + kw_ - 1;                               \
        bool val_ = ((unsigned)yy_ < (unsigned)H) && ((unsigned)xx_ < (unsigned)W); \
        int vsz_ = val_ ? 16 : 0;                                               \
        long ao_ = ((long)(b*H + (val_?yy_:0))*W + (val_?xx_:0))*FC + cc_ + sbase*8; \
        uint32_t ab_ = sb + 2048u + (uint32_t)(buf)*BUFSZ + lr*144 + sbase*16;  \
        const __nv_bfloat16* ah_ = inh + ao_;                                   \
        const __nv_bfloat16* al_ = inl + ao_;                                   \
        _Pragma("unroll")                                                       \
        for (int j_ = 0; j_ < 4; j_++) {                                        \
            cp16(ab_ + j_*16,       ah_ + j_*8, vsz_);                          \
            cp16(ab_ + APS + j_*16, al_ + j_*8, vsz_);                          \
        }                                                                       \
        long bo_ = ((long)((kh_*3+kw_)*FC + tid))*FC + cc_;                     \
        const __nv_bfloat16* bh_ = wh + bo_;                                    \
        const __nv_bfloat16* bl_ = wl + bo_;                                    \
        uint32_t bb_ = sb + 2048u + (uint32_t)(buf)*BUFSZ + 2*APS + tid*144;    \
        _Pragma("unroll")                                                       \
        for (int j_ = 0; j_ < 8; j_++) {                                        \
            cp16(bb_ + j_*16,       bh_ + j_*8, 16);                            \
            cp16(bb_ + BPS + j_*16, bl_ + j_*8, 16);                            \
        }                                                                       \
    } while (0)

__global__ __launch_bounds__(256, 1)
void conv_mma(const __nv_bfloat16* __restrict__ inh, const __nv_bfloat16* __restrict__ inl,
              const __nv_bfloat16* __restrict__ wh,  const __nv_bfloat16* __restrict__ wl,
              const float* __restrict__ bnp, float* __restrict__ out, int H, int W) {
    extern __shared__ char sm[];
    float* bsc = (float*)sm;
    float* bshf = (float*)(sm + 1024);
    uint32_t sb = smem_u32(sm);
    int tid = threadIdx.x;
    int lane = tid & 31, wid = tid >> 5;
    const int HW = H*W;
    int m0 = blockIdx.x * 128;

    {
        float g = bnp[tid], be = bnp[256+tid], mu = bnp[512+tid], va = bnp[768+tid];
        float sc = g * rsqrtf(va + 1e-5f);
        bsc[tid] = sc; bshf[tid] = be - mu*sc;
    }

    // A load geometry: row lr (0..127), 2 threads/row, 4 segs each
    int lr = tid >> 1;
    int sbase = (tid & 1) * 4;
    int mrow = m0 + lr;
    int b = mrow / HW;
    int s = mrow - b*HW;
    int y = s / W, x = s - y*W;

    // warp compute geometry: 2(M) x 4(N), warp tile 64x64
    int wm = wid >> 2;             // 0..1   (64 M rows each)
    int wn = wid & 3;              // 0..3   (64 N cols each)
    int alr = lane & 15;
    int alc = (lane >> 4) << 4;
    int bg = lane >> 3;
    int brow_off = ((bg >> 1) << 3) + (lane & 7);
    int bcol = (bg & 1) << 4;

    float acc[4][8][4];
    #pragma unroll
    for (int i=0;i<4;i++)
        #pragma unroll
        for (int j=0;j<8;j++)
            #pragma unroll
            for (int k=0;k<4;k++) acc[i][j][k]=0.f;

    LOAD_CHUNK(0, 0);
    CP_COMMIT();

    for (int ci = 0; ci < 36; ci++) {
        int buf = ci & 1;
        if (ci < 35) {
            LOAD_CHUNK(ci+1, (ci+1)&1);
            CP_COMMIT();
            CP_WAIT(1);
        } else {
            CP_WAIT(0);
        }
        __syncthreads();

        uint32_t base = sb + 2048u + (uint32_t)buf*BUFSZ;
        #pragma unroll
        for (int k16 = 0; k16 < 4; k16++) {
            uint32_t ah4[4][4], al4[4][4];
            #pragma unroll
            for (int mt = 0; mt < 4; mt++) {
                uint32_t aaddr = base + (uint32_t)((wm*64 + mt*16 + alr)*144 + k16*32 + alc);
                ldm_x4(ah4[mt], aaddr);
                ldm_x4(al4[mt], aaddr + APS);
            }
            #pragma unroll
            for (int np = 0; np < 4; np++) {
                uint32_t baddr = base + 2*APS +
                    (uint32_t)((wn*64 + np*16 + brow_off)*144 + k16*32 + bcol);
                uint32_t th[4], tl[4];
                ldm_x4(th, baddr);
                ldm_x4(tl, baddr + BPS);
                uint32_t bh0[2] = {th[0], th[1]}, bh1[2] = {th[2], th[3]};
                uint32_t bl0[2] = {tl[0], tl[1]}, bl1[2] = {tl[2], tl[3]};
                #pragma unroll
                for (int mt = 0; mt < 4; mt++) {
                    mma_bf16(acc[mt][np*2],   ah4[mt], bh0);
                    mma_bf16(acc[mt][np*2],   ah4[mt], bl0);
                    mma_bf16(acc[mt][np*2],   al4[mt], bh0);
                    mma_bf16(acc[mt][np*2+1], ah4[mt], bh1);
                    mma_bf16(acc[mt][np*2+1], ah4[mt], bl1);
                    mma_bf16(acc[mt][np*2+1], al4[mt], bh1);
                }
            }
        }
        __syncthreads();
    }

    // epilogue: BN + ReLU, HWC float2 stores
    #pragma unroll
    for (int mt = 0; mt < 4; mt++) {
        int rbase = m0 + wm*64 + mt*16 + (lane >> 2);
        #pragma unroll
        for (int h2 = 0; h2 < 2; h2++) {
            int mr = rbase + h2*8;
            int bb2 = mr / HW;
            int ss  = mr - bb2*HW;
            float* op = out + ((size_t)bb2*HW + ss)*FC;
            #pragma unroll
            for (int nt = 0; nt < 8; nt++) {
                int n = wn*64 + nt*8 + (lane & 3)*2;
                float2 v;
                v.x = fmaxf(fmaf(acc[mt][nt][h2*2+0], bsc[n],   bshf[n]),   0.f);
                v.y = fmaxf(fmaf(acc[mt][nt][h2*2+1], bsc[n+1], bshf[n+1]), 0.f);
                *(float2*)(op + n) = v;
            }
        }
    }
}

// =====================================================================
// Kernel 6: head conv 3x3, 256 -> 1, + bias (HWC in)
// =====================================================================
__global__ __launch_bounds__(256)
void outconv_kernel(const float* __restrict__ in, const float* __restrict__ wv,
                    const float* __restrict__ bias, float* __restrict__ out,
                    int H, int W) {
    __shared__ float ws2[9*FC];   // [j][c]
    int tid = threadIdx.x;
    for (int i = tid; i < 9*FC; i += 256) {
        int j = i >> 8, c = i & 255;
        ws2[i] = wv[c*9 + j];
    }
    __syncthreads();
    int HW = H*W;
    int idx = blockIdx.x*256 + tid;
    int s = idx % HW;
    int b = idx / HW;
    int y = s / W, x = s % W;
    float acc = __ldg(bias);
    #pragma unroll
    for (int kh = 0; kh < 3; kh++) {
        int iy = y + kh - 1;
        if ((unsigned)iy >= (unsigned)H) continue;
        #pragma unroll
        for (int kw = 0; kw < 3; kw++) {
            int ix = x + kw - 1;
            if ((unsigned)ix >= (unsigned)W) continue;
            const float4* ip = (const float4*)(in + ((size_t)(b*H + iy)*W + ix)*FC);
            const float4* wp = (const float4*)(ws2 + (kh*3 + kw)*FC);
            #pragma unroll 8
            for (int c = 0; c < 64; c++) {
                float4 a = ip[c], w4 = wp[c];
                acc = fmaf(a.x, w4.x, acc); acc = fmaf(a.y, w4.y, acc);
                acc = fmaf(a.z, w4.z, acc); acc = fmaf(a.w, w4.w, acc);
            }
        }
    }
    out[idx] = acc;
}

// =====================================================================
// launcher
// =====================================================================
extern "C" void kernel_launch(void* const* d_in, const int* in_sizes, int n_in,
                              void* d_out, int out_size) {
    const float* f1  = (const float*)d_in[0];
    const float* f2  = (const float*)d_in[1];
    const float* f3  = (const float*)d_in[2];
    const float* f4  = (const float*)d_in[3];
    const float* pw  = (const float*)d_in[4];
    const float* lw  = (const float*)d_in[5];
    const float* dww = (const float*)d_in[6];
    const float* bne = (const float*)d_in[7];
    const float* ow1 = (const float*)d_in[8];
    const float* ob1 = (const float*)d_in[9];
    const float* cw1 = (const float*)d_in[10];
    const float* bn1 = (const float*)d_in[11];
    const float* ow2 = (const float*)d_in[12];
    const float* ob2 = (const float*)d_in[13];
    const float* cw2 = (const float*)d_in[14];
    const float* bn2 = (const float*)d_in[15];
    const float* owv = (const float*)d_in[16];
    const float* obv = (const float*)d_in[17];
    float* outp = (float*)d_out;

    float *px0, *penh, *poff, *pc1, *pc2;
    __nv_bfloat16 *puh, *pul, *pw1h, *pw1l, *pw2h, *pw2l;
    cudaGetSymbolAddress((void**)&px0,  g_x0t);
    cudaGetSymbolAddress((void**)&penh, g_enht);
    cudaGetSymbolAddress((void**)&poff, g_off);
    cudaGetSymbolAddress((void**)&puh,  g_uph);
    cudaGetSymbolAddress((void**)&pul,  g_upl);
    cudaGetSymbolAddress((void**)&pc1,  g_c1t);
    cudaGetSymbolAddress((void**)&pc2,  g_c2t);
    cudaGetSymbolAddress((void**)&pw1h, g_w1h);
    cudaGetSymbolAddress((void**)&pw1l, g_w1l);
    cudaGetSymbolAddress((void**)&pw2h, g_w2h);
    cudaGetSymbolAddress((void**)&pw2l, g_w2l);

    cudaFuncSetAttribute(conv_mma, cudaFuncAttributeMaxDynamicSharedMemorySize, CONV_SMEM);

    // 0) pre-split conv weights to bf16 hi/lo
    wconv_kernel<<<2304, 256>>>(cw1, pw1h, pw1l);
    wconv_kernel<<<2304, 256>>>(cw2, pw2h, pw2l);
    // 1) weighted fusion GEMM + GELU -> HWC (B,32,32,256)
    fusion_kernel<<<dim3(64, 4), 256>>>(f1, f2, f3, f4, pw, lw, px0);
    // 2) depthwise enhancer (HWC)
    enhance_kernel<<<4096, 256>>>(px0, dww, bne, penh);
    // 3) stage 1: offsets, upsample to 64x64 (bf16 hi/lo), warp-MMA conv
    offset_kernel  <<<512,   256>>>(penh, ow1, ob1, poff, 32, 32);
    upsample_kernel<<<16384, 256>>>(penh, poff, puh, pul, 32, 32);
    conv_mma<<<128, 256, CONV_SMEM>>>(puh, pul, pw1h, pw1l, bn1, pc1, 64, 64);
    // 4) stage 2: offsets, upsample to 128x128, warp-MMA conv
    offset_kernel  <<<2048,  256>>>(pc1, ow2, ob2, poff, 64, 64);
    upsample_kernel<<<65536, 256>>>(pc1, poff, puh, pul, 64, 64);
    conv_mma<<<512, 256, CONV_SMEM>>>(puh, pul, pw2h, pw2l, bn2, pc2, 128, 128);
    // 5) depth head (HWC reduction)
    outconv_kernel <<<256, 256>>>(pc2, owv, obv, outp, 128, 128);
}

// round 16
// speedup vs baseline: 2.1015x; 1.2088x over previous
#include <cuda_runtime.h>
#include <cuda_bf16.h>
#include <math.h>
#include <stdint.h>

// ---------------- problem constants ----------------
#define BN  4
#define CIN 768
#define FC  256
#define N0  1024   // 32*32

// ---------------- scratch (device globals; no allocations allowed) ----------------
// HWC layouts: [(b*H + y)*W + x][c]
__device__ float g_x0t [BN*N0*FC];                 //  4 MB fusion out (HWC, 32x32)
__device__ float g_enht[BN*N0*FC];                 //  4 MB enhanced   (HWC, 32x32)
__device__ float g_off [BN*32*64*64];              //  2 MB offsets (NCHW, max stage-2)
__device__ __nv_bfloat16 g_uph[BN*128*128*FC];     // 33.5 MB upsampled hi (HWC bf16)
__device__ __nv_bfloat16 g_upl[BN*128*128*FC];     // 33.5 MB upsampled lo
__device__ float g_c1t [BN*64*64*FC];              // 16 MB conv1 out (HWC)
__device__ float g_c2t [BN*128*128*FC];            // 64 MB conv2 out (HWC)
// pre-split conv weights: [(kh*3+kw)*256 + n][c] bf16
__device__ __nv_bfloat16 g_w1h[9*FC*FC], g_w1l[9*FC*FC];
__device__ __nv_bfloat16 g_w2h[9*FC*FC], g_w2l[9*FC*FC];

__device__ __forceinline__ float gelu_exact(float x) {
    return 0.5f * x * (1.0f + erff(x * 0.70710678118654752440f));
}

// ---------------- packed fp32x2 helpers (fusion kernel) ----------------
typedef unsigned long long ull;
__device__ __forceinline__ ull pack_dup(float a) {
    ull r; asm("mov.b64 %0, {%1, %1};" : "=l"(r) : "f"(a)); return r;
}
__device__ __forceinline__ void unpack2(float& lo, float& hi, ull v) {
    asm("mov.b64 {%0, %1}, %2;" : "=f"(lo), "=f"(hi) : "l"(v));
}
#define FFMA2(d, a, b) asm("fma.rn.f32x2 %0, %1, %2, %0;" : "+l"(d) : "l"(a), "l"(b))

// ---------------- warp-MMA helpers (sm_80+ path; no 'a'-gated instructions) ------
__device__ __forceinline__ uint32_t smem_u32(const void* p) {
    return (uint32_t)__cvta_generic_to_shared(p);
}
__device__ __forceinline__ void mma_bf16(float* c, const uint32_t* a, const uint32_t* b) {
    asm volatile(
        "mma.sync.aligned.m16n8k16.row.col.f32.bf16.bf16.f32 "
        "{%0,%1,%2,%3}, {%4,%5,%6,%7}, {%8,%9}, {%0,%1,%2,%3};"
        : "+f"(c[0]), "+f"(c[1]), "+f"(c[2]), "+f"(c[3])
        : "r"(a[0]), "r"(a[1]), "r"(a[2]), "r"(a[3]), "r"(b[0]), "r"(b[1]));
}
__device__ __forceinline__ void ldm_x4(uint32_t* r, uint32_t addr) {
    asm volatile("ldmatrix.sync.aligned.m8n8.x4.shared.b16 {%0,%1,%2,%3}, [%4];"
        : "=r"(r[0]), "=r"(r[1]), "=r"(r[2]), "=r"(r[3]) : "r"(addr));
}
__device__ __forceinline__ void cp16(uint32_t dst, const void* src, int sz) {
    asm volatile("cp.async.cg.shared.global [%0], [%1], 16, %2;"
        :: "r"(dst), "l"(src), "r"(sz));
}
#define CP_COMMIT() asm volatile("cp.async.commit_group;" ::: "memory")
#define CP_WAIT(N)  asm volatile("cp.async.wait_group %0;" :: "n"(N) : "memory")

// =====================================================================
// Kernel 0: weight pre-split: OIHW fp32 -> [(kh3+kw)*256+n][c] bf16 hi/lo
// =====================================================================
__global__ __launch_bounds__(256)
void wconv_kernel(const float* __restrict__ w, __nv_bfloat16* __restrict__ oh,
                  __nv_bfloat16* __restrict__ ol) {
    int idx = blockIdx.x * 256 + threadIdx.x;  // = (j*256 + n)*256 + c
    int c = idx & 255;
    int n = (idx >> 8) & 255;
    int j = idx >> 16;
    float v = w[((n << 8) + c) * 9 + j];
    __nv_bfloat16 hi = __float2bfloat16_rn(v);
    oh[idx] = hi;
    ol[idx] = __float2bfloat16_rn(v - __bfloat162float(hi));
}

// =====================================================================
// Kernel 1: weighted fusion (FFMA2 GEMM) -> HWC output
// =====================================================================
__global__ __launch_bounds__(256)
void fusion_kernel(const float* __restrict__ f1, const float* __restrict__ f2,
                   const float* __restrict__ f3, const float* __restrict__ f4,
                   const float* __restrict__ pw, const float* __restrict__ lwr,
                   float* __restrict__ out) {
    __shared__ float As[16][64];
    __shared__ float Bs[16][64];
    const float* fs[4] = {f1, f2, f3, f4};

    float l0 = __ldg(lwr), l1 = __ldg(lwr+1), l2 = __ldg(lwr+2), l3 = __ldg(lwr+3);
    float mx = fmaxf(fmaxf(l0,l1), fmaxf(l2,l3));
    float e0 = expf(l0-mx), e1 = expf(l1-mx), e2 = expf(l2-mx), e3 = expf(l3-mx);
    float inv = 1.0f/(e0+e1+e2+e3);
    float lw[4] = {e0*inv, e1*inv, e2*inv, e3*inv};

    int tid = threadIdx.x;
    int tx = tid & 15, ty = tid >> 4;
    int m0 = blockIdx.x * 64;
    int fo0 = blockIdx.y * 64;
    int b  = m0 >> 10;
    int nb = m0 & 1023;
    int lm = tid & 63;
    int lk = tid >> 6;

    float outacc[4][4];
    #pragma unroll
    for (int i=0;i<4;i++)
        #pragma unroll
        for (int j=0;j<4;j++) outacc[i][j]=0.f;

    #pragma unroll
    for (int l = 0; l < 4; l++) {
        const float* A  = fs[l] + b * CIN * N0 + nb;
        const float* Wl = pw + l * CIN * FC + fo0;
        ull acc2[4][2];
        #pragma unroll
        for (int i=0;i<4;i++) { acc2[i][0]=0ULL; acc2[i][1]=0ULL; }

        for (int k0 = 0; k0 < CIN; k0 += 16) {
            #pragma unroll
            for (int i = 0; i < 4; i++) {
                int kk = lk + i*4;
                As[kk][lm] = A [(k0+kk)*N0 + lm];
                Bs[kk][lm] = Wl[(k0+kk)*FC + lm];
            }
            __syncthreads();
            #pragma unroll
            for (int kk = 0; kk < 16; kk++) {
                float4 av = *(const float4*)&As[kk][tx*4];
                ulonglong2 bq = *(const ulonglong2*)&Bs[kk][ty*4];
                ull ad[4] = {pack_dup(av.x), pack_dup(av.y),
                             pack_dup(av.z), pack_dup(av.w)};
                #pragma unroll
                for (int i=0;i<4;i++) {
                    FFMA2(acc2[i][0], ad[i], bq.x);
                    FFMA2(acc2[i][1], ad[i], bq.y);
                }
            }
            __syncthreads();
        }
        float wl = lw[l];
        #pragma unroll
        for (int i=0;i<4;i++)
            #pragma unroll
            for (int jp=0;jp<2;jp++) {
                float vlo, vhi;
                unpack2(vlo, vhi, acc2[i][jp]);
                outacc[i][2*jp+0] = fmaf(wl, gelu_exact(vlo), outacc[i][2*jp+0]);
                outacc[i][2*jp+1] = fmaf(wl, gelu_exact(vhi), outacc[i][2*jp+1]);
            }
    }
    // HWC write: out[(b*1024 + spatial)*256 + f], contiguous in f
    #pragma unroll
    for (int i = 0; i < 4; i++) {
        int sp = nb + tx*4 + i;
        float4 v = make_float4(outacc[i][0], outacc[i][1], outacc[i][2], outacc[i][3]);
        *(float4*)&out[((size_t)b*N0 + sp)*FC + fo0 + ty*4] = v;
    }
}

// =====================================================================
// Kernel 2: depthwise 3x3 + BN + residual ReLU (HWC, 32x32)
// =====================================================================
__global__ __launch_bounds__(256)
void enhance_kernel(const float* __restrict__ x, const float* __restrict__ dw,
                    const float* __restrict__ bnp, float* __restrict__ out) {
    __shared__ float dws[FC*9];
    __shared__ float bsc[FC], bsh[FC];
    int tid = threadIdx.x;
    for (int i = tid; i < FC*9; i += 256) dws[i] = dw[i];
    {
        float g = bnp[tid], be = bnp[256+tid], mu = bnp[512+tid], va = bnp[768+tid];
        float sc = g * rsqrtf(va + 1e-5f);
        bsc[tid] = sc; bsh[tid] = be - mu*sc;
    }
    __syncthreads();
    int idx = blockIdx.x * 256 + tid;          // (b*1024 + s)*256 + c
    int c = idx & 255;
    int sp = idx >> 8;
    int s = sp & 1023;
    int w = s & 31, h = s >> 5;
    float xc = x[idx];
    float y = 0.f;
    #pragma unroll
    for (int kh = 0; kh < 3; kh++) {
        int iy = h + kh - 1;
        if ((unsigned)iy < 32u) {
            #pragma unroll
            for (int kw = 0; kw < 3; kw++) {
                int ix = w + kw - 1;
                if ((unsigned)ix < 32u)
                    y = fmaf(dws[c*9 + kh*3 + kw],
                             x[((sp - s) + (iy<<5) + ix)*FC + c], y);
            }
        }
    }
    out[idx] = fmaxf(fmaf(y, bsc[c], bsh[c]) + xc, 0.f);
}

// =====================================================================
// Kernel 3: 1x1 offset conv (HWC in, 256 -> 32) + bias. Warp-per-pixel.
// =====================================================================
__global__ __launch_bounds__(256)
void offset_kernel(const float* __restrict__ in, const float* __restrict__ ow,
                   const float* __restrict__ ob, float* __restrict__ off,
                   int H, int W) {
    __shared__ float ws[FC*32];   // [c][j]
    int tid = threadIdx.x;
    for (int i = tid; i < FC*32; i += 256) {
        int c = i >> 5, j = i & 31;
        ws[i] = ow[j*FC + c];
    }
    __syncthreads();
    int HW = H*W;
    int wid = tid >> 5, j = tid & 31;
    int p = blockIdx.x * 8 + wid;              // pixel in [0, BN*HW)
    const float4* ip = (const float4*)(in + (size_t)p*FC);
    float acc = __ldg(&ob[j]);
    #pragma unroll 4
    for (int c4 = 0; c4 < 64; c4++) {
        float4 v = ip[c4];                     // uniform across warp -> broadcast
        int c = c4 * 4;
        acc = fmaf(v.x, ws[(c+0)*32 + j], acc);
        acc = fmaf(v.y, ws[(c+1)*32 + j], acc);
        acc = fmaf(v.z, ws[(c+2)*32 + j], acc);
        acc = fmaf(v.w, ws[(c+3)*32 + j], acc);
    }
    int b = p / HW, s = p - b*HW;
    off[(b*32 + j)*HW + s] = acc;
}

// =====================================================================
// Kernel 4: DySample bilinear gather, 4 channels/thread (shared offsets,
// float4 gathers, packed bf16x4 stores). HWC fp32 in, bf16 hi/lo out.
// =====================================================================
__global__ __launch_bounds__(256)
void upsample_kernel(const float* __restrict__ x, const float* __restrict__ off,
                     __nv_bfloat16* __restrict__ oh, __nv_bfloat16* __restrict__ ol,
                     int H, int W) {
    int W2 = 2*W, H2 = 2*H, HW = H*W;
    int idx = blockIdx.x*256 + threadIdx.x;   // (sp)*64 + c4grp
    int cg = idx & 63;                         // channel group: 4 ch each
    int c  = cg << 2;
    int sp = idx >> 6;
    int wo = sp % W2;
    int t  = sp / W2;
    int ho = t % H2;
    int b  = t / H2;
    int g  = c >> 6;
    int h = ho >> 1, dh = ho & 1, w = wo >> 1, dw = wo & 1;
    int obase = ((b*32 + g*4 + dh*2 + dw)*H + h)*W + w;
    float offx = off[obase]         * 0.25f + (0.5f*(float)dw - 0.25f);
    float offy = off[obase + 16*HW] * 0.25f + (0.5f*(float)dh - 0.25f);
    float px = fminf(fmaxf((float)w + offx, 0.f), (float)(W-1));
    float py = fminf(fmaxf((float)h + offy, 0.f), (float)(H-1));
    int x0 = (int)px;
    int y0 = (int)py;
    float wx = px - (float)x0, wy = py - (float)y0;
    int x1 = min(x0+1, W-1);
    int y1 = min(y0+1, H-1);
    const float* ib = x + (size_t)b*HW*FC + c;
    float4 v00 = *(const float4*)(ib + ((size_t)y0*W + x0)*FC);
    float4 v01 = *(const float4*)(ib + ((size_t)y0*W + x1)*FC);
    float4 v10 = *(const float4*)(ib + ((size_t)y1*W + x0)*FC);
    float4 v11 = *(const float4*)(ib + ((size_t)y1*W + x1)*FC);
    float vr[4];
    vr[0] = (v00.x + (v01.x-v00.x)*wx) + ((v10.x + (v11.x-v10.x)*wx) - (v00.x + (v01.x-v00.x)*wx))*wy;
    vr[1] = (v00.y + (v01.y-v00.y)*wx) + ((v10.y + (v11.y-v10.y)*wx) - (v00.y + (v01.y-v00.y)*wx))*wy;
    vr[2] = (v00.z + (v01.z-v00.z)*wx) + ((v10.z + (v11.z-v10.z)*wx) - (v00.z + (v01.z-v00.z)*wx))*wy;
    vr[3] = (v00.w + (v01.w-v00.w)*wx) + ((v10.w + (v11.w-v10.w)*wx) - (v00.w + (v01.w-v00.w)*wx))*wy;
    __nv_bfloat16 hi[4], lo[4];
    #pragma unroll
    for (int i = 0; i < 4; i++) {
        hi[i] = __float2bfloat16_rn(vr[i]);
        lo[i] = __float2bfloat16_rn(vr[i] - __bfloat162float(hi[i]));
    }
    size_t o = (size_t)sp*FC + c;
    *(uint2*)(oh + o) = *(uint2*)hi;
    *(uint2*)(ol + o) = *(uint2*)lo;
}

// =====================================================================
// Kernel 5: 3x3 conv 256->256, warp-MMA bf16-split implicit GEMM + BN + ReLU.
// v3 (occupancy probe): CTA tile 128(M) x 128(N), KT=32 -> 72 chunks,
// SMEM 84KB double-buffered -> 2 CTAs/SM. Same 3-term split math as v1.
// Planes: Ah, Al, Bh, Bl: 128 rows x 80B (64B data + 16B pad; ldmatrix
// conflict-free: (r*20)%32 distinct over 8 rows).
// =====================================================================
#define APS 10240                     // plane stride: 128*80
#define BUFSZ (4*APS)                 // 40960
#define CONV_SMEM (2048 + 2*BUFSZ)    // 83968

#define LOAD_CHUNK(ci, buf)                                                     \
    do {                                                                        \
        int tap_ = (ci) >> 3, cc_ = ((ci) & 7) << 5;                            \
        int kh_ = tap_ / 3, kw_ = tap_ - kh_*3;                                 \
        int yy_ = y + kh_ - 1, xx_ = x + kw_ - 1;                               \
        bool val_ = ((unsigned)yy_ < (unsigned)H) && ((unsigned)xx_ < (unsigned)W); \
        int vsz_ = val_ ? 16 : 0;                                               \
        long ao_ = ((long)(b*H + (val_?yy_:0))*W + (val_?xx_:0))*FC + cc_ + hseg*8; \
        uint32_t ab_ = sb + 2048u + (uint32_t)(buf)*BUFSZ + lr*80 + hseg*16;    \
        const __nv_bfloat16* ah_ = inh + ao_;                                   \
        const __nv_bfloat16* al_ = inl + ao_;                                   \
        long bo_ = ((long)(tap_*FC + n0c + lr))*FC + cc_ + hseg*8;              \
        const __nv_bfloat16* bh_ = wh + bo_;                                    \
        const __nv_bfloat16* bl_ = wl + bo_;                                    \
        _Pragma("unroll")                                                       \
        for (int j_ = 0; j_ < 2; j_++) {                                        \
            cp16(ab_ + j_*16,         ah_ + j_*8, vsz_);                        \
            cp16(ab_ + APS + j_*16,   al_ + j_*8, vsz_);                        \
            cp16(ab_ + 2*APS + j_*16, bh_ + j_*8, 16);                          \
            cp16(ab_ + 3*APS + j_*16, bl_ + j_*8, 16);                          \
        }                                                                       \
    } while (0)

__global__ __launch_bounds__(256, 2)
void conv_mma(const __nv_bfloat16* __restrict__ inh, const __nv_bfloat16* __restrict__ inl,
              const __nv_bfloat16* __restrict__ wh,  const __nv_bfloat16* __restrict__ wl,
              const float* __restrict__ bnp, float* __restrict__ out, int H, int W) {
    extern __shared__ char sm[];
    float* bsc = (float*)sm;
    float* bshf = (float*)(sm + 1024);
    uint32_t sb = smem_u32(sm);
    int tid = threadIdx.x;
    int lane = tid & 31, wid = tid >> 5;
    const int HW = H*W;
    int m0 = blockIdx.x * 128;
    int n0c = blockIdx.y * 128;

    {
        float g = bnp[tid], be = bnp[256+tid], mu = bnp[512+tid], va = bnp[768+tid];
        float sc = g * rsqrtf(va + 1e-5f);
        bsc[tid] = sc; bshf[tid] = be - mu*sc;
    }

    // load geometry: row lr (0..127), 2 threads/row, 2x16B segs each
    int lr = tid >> 1;
    int hseg = (tid & 1) * 2;
    int mrow = m0 + lr;
    int b = mrow / HW;
    int s = mrow - b*HW;
    int y = s / W, x = s - y*W;

    // warp compute geometry: 4(M) x 2(N), warp tile 32x64
    int wm = wid & 3;
    int wn = wid >> 2;
    int alr = lane & 15;
    int alc = (lane >> 4) << 4;
    int bg = lane >> 3;
    int brow_off = ((bg >> 1) << 3) + (lane & 7);
    int bcol = (bg & 1) << 4;

    float acc[2][8][4];
    #pragma unroll
    for (int i=0;i<2;i++)
        #pragma unroll
        for (int j=0;j<8;j++)
            #pragma unroll
            for (int k=0;k<4;k++) acc[i][j][k]=0.f;

    LOAD_CHUNK(0, 0);
    CP_COMMIT();

    for (int ci = 0; ci < 72; ci++) {
        int buf = ci & 1;
        if (ci < 71) {
            LOAD_CHUNK(ci+1, (ci+1)&1);
            CP_COMMIT();
            CP_WAIT(1);
        } else {
            CP_WAIT(0);
        }
        __syncthreads();

        uint32_t base = sb + 2048u + (uint32_t)buf*BUFSZ;
        #pragma unroll
        for (int k16 = 0; k16 < 2; k16++) {
            uint32_t ah4[2][4], al4[2][4];
            #pragma unroll
            for (int mt = 0; mt < 2; mt++) {
                uint32_t aaddr = base + (uint32_t)((wm*32 + mt*16 + alr)*80 + k16*32 + alc);
                ldm_x4(ah4[mt], aaddr);
                ldm_x4(al4[mt], aaddr + APS);
            }
            #pragma unroll
            for (int np = 0; np < 4; np++) {
                uint32_t baddr = base + 2*APS +
                    (uint32_t)((wn*64 + np*16 + brow_off)*80 + k16*32 + bcol);
                uint32_t th[4], tl[4];
                ldm_x4(th, baddr);
                ldm_x4(tl, baddr + APS);
                uint32_t bh0[2] = {th[0], th[1]}, bh1[2] = {th[2], th[3]};
                uint32_t bl0[2] = {tl[0], tl[1]}, bl1[2] = {tl[2], tl[3]};
                #pragma unroll
                for (int mt = 0; mt < 2; mt++) {
                    mma_bf16(acc[mt][np*2],   ah4[mt], bh0);
                    mma_bf16(acc[mt][np*2],   ah4[mt], bl0);
                    mma_bf16(acc[mt][np*2],   al4[mt], bh0);
                    mma_bf16(acc[mt][np*2+1], ah4[mt], bh1);
                    mma_bf16(acc[mt][np*2+1], ah4[mt], bl1);
                    mma_bf16(acc[mt][np*2+1], al4[mt], bh1);
                }
            }
        }
        __syncthreads();
    }

    // epilogue: BN + ReLU, HWC float2 stores
    #pragma unroll
    for (int mt = 0; mt < 2; mt++) {
        int rbase = m0 + wm*32 + mt*16 + (lane >> 2);
        #pragma unroll
        for (int h2 = 0; h2 < 2; h2++) {
            int mr = rbase + h2*8;
            int bb2 = mr / HW;
            int ss  = mr - bb2*HW;
            float* op = out + ((size_t)bb2*HW + ss)*FC;
            #pragma unroll
            for (int nt = 0; nt < 8; nt++) {
                int n = n0c + wn*64 + nt*8 + (lane & 3)*2;
                float2 v;
                v.x = fmaxf(fmaf(acc[mt][nt][h2*2+0], bsc[n],   bshf[n]),   0.f);
                v.y = fmaxf(fmaf(acc[mt][nt][h2*2+1], bsc[n+1], bshf[n+1]), 0.f);
                *(float2*)(op + n) = v;
            }
        }
    }
}

// =====================================================================
// Kernel 6: head conv 3x3, 256 -> 1, + bias (HWC in)
// =====================================================================
__global__ __launch_bounds__(256)
void outconv_kernel(const float* __restrict__ in, const float* __restrict__ wv,
                    const float* __restrict__ bias, float* __restrict__ out,
                    int H, int W) {
    __shared__ float ws2[9*FC];   // [j][c]
    int tid = threadIdx.x;
    for (int i = tid; i < 9*FC; i += 256) {
        int j = i >> 8, c = i & 255;
        ws2[i] = wv[c*9 + j];
    }
    __syncthreads();
    int HW = H*W;
    int idx = blockIdx.x*256 + tid;
    int s = idx % HW;
    int b = idx / HW;
    int y = s / W, x = s % W;
    float acc = __ldg(bias);
    #pragma unroll
    for (int kh = 0; kh < 3; kh++) {
        int iy = y + kh - 1;
        if ((unsigned)iy >= (unsigned)H) continue;
        #pragma unroll
        for (int kw = 0; kw < 3; kw++) {
            int ix = x + kw - 1;
            if ((unsigned)ix >= (unsigned)W) continue;
            const float4* ip = (const float4*)(in + ((size_t)(b*H + iy)*W + ix)*FC);
            const float4* wp = (const float4*)(ws2 + (kh*3 + kw)*FC);
            #pragma unroll 8
            for (int c = 0; c < 64; c++) {
                float4 a = ip[c], w4 = wp[c];
                acc = fmaf(a.x, w4.x, acc); acc = fmaf(a.y, w4.y, acc);
                acc = fmaf(a.z, w4.z, acc); acc = fmaf(a.w, w4.w, acc);
            }
        }
    }
    out[idx] = acc;
}

// =====================================================================
// launcher
// =====================================================================
extern "C" void kernel_launch(void* const* d_in, const int* in_sizes, int n_in,
                              void* d_out, int out_size) {
    const float* f1  = (const float*)d_in[0];
    const float* f2  = (const float*)d_in[1];
    const float* f3  = (const float*)d_in[2];
    const float* f4  = (const float*)d_in[3];
    const float* pw  = (const float*)d_in[4];
    const float* lw  = (const float*)d_in[5];
    const float* dww = (const float*)d_in[6];
    const float* bne = (const float*)d_in[7];
    const float* ow1 = (const float*)d_in[8];
    const float* ob1 = (const float*)d_in[9];
    const float* cw1 = (const float*)d_in[10];
    const float* bn1 = (const float*)d_in[11];
    const float* ow2 = (const float*)d_in[12];
    const float* ob2 = (const float*)d_in[13];
    const float* cw2 = (const float*)d_in[14];
    const float* bn2 = (const float*)d_in[15];
    const float* owv = (const float*)d_in[16];
    const float* obv = (const float*)d_in[17];
    float* outp = (float*)d_out;

    float *px0, *penh, *poff, *pc1, *pc2;
    __nv_bfloat16 *puh, *pul, *pw1h, *pw1l, *pw2h, *pw2l;
    cudaGetSymbolAddress((void**)&px0,  g_x0t);
    cudaGetSymbolAddress((void**)&penh, g_enht);
    cudaGetSymbolAddress((void**)&poff, g_off);
    cudaGetSymbolAddress((void**)&puh,  g_uph);
    cudaGetSymbolAddress((void**)&pul,  g_upl);
    cudaGetSymbolAddress((void**)&pc1,  g_c1t);
    cudaGetSymbolAddress((void**)&pc2,  g_c2t);
    cudaGetSymbolAddress((void**)&pw1h, g_w1h);
    cudaGetSymbolAddress((void**)&pw1l, g_w1l);
    cudaGetSymbolAddress((void**)&pw2h, g_w2h);
    cudaGetSymbolAddress((void**)&pw2l, g_w2l);

    cudaFuncSetAttribute(conv_mma, cudaFuncAttributeMaxDynamicSharedMemorySize, CONV_SMEM);

    // 0) pre-split conv weights to bf16 hi/lo
    wconv_kernel<<<2304, 256>>>(cw1, pw1h, pw1l);
    wconv_kernel<<<2304, 256>>>(cw2, pw2h, pw2l);
    // 1) weighted fusion GEMM + GELU -> HWC (B,32,32,256)
    fusion_kernel<<<dim3(64, 4), 256>>>(f1, f2, f3, f4, pw, lw, px0);
    // 2) depthwise enhancer (HWC)
    enhance_kernel<<<4096, 256>>>(px0, dww, bne, penh);
    // 3) stage 1: offsets, upsample to 64x64 (bf16 hi/lo), warp-MMA conv
    offset_kernel  <<<512,  256>>>(penh, ow1, ob1, poff, 32, 32);
    upsample_kernel<<<4096, 256>>>(penh, poff, puh, pul, 32, 32);
    conv_mma<<<dim3(128, 2), 256, CONV_SMEM>>>(puh, pul, pw1h, pw1l, bn1, pc1, 64, 64);
    // 4) stage 2: offsets, upsample to 128x128, warp-MMA conv
    offset_kernel  <<<2048,  256>>>(pc1, ow2, ob2, poff, 64, 64);
    upsample_kernel<<<16384, 256>>>(pc1, poff, puh, pul, 64, 64);
    conv_mma<<<dim3(512, 2), 256, CONV_SMEM>>>(puh, pul, pw2h, pw2l, bn2, pc2, 128, 128);
    // 5) depth head (HWC reduction)
    outconv_kernel <<<256, 256>>>(pc2, owv, obv, outp, 128, 128);
}